// round 7
// baseline (speedup 1.0000x reference)
#include <cuda_runtime.h>
#include <math.h>
#include <stdint.h>

#define B_   2
#define T_   2048
#define C_   2048
#define H_   16
#define KVH_ 4
#define HD_  128
#define MROWS (B_*T_)   // 4096

// ---------------- scratch (device globals; no allocations) ----------------
__device__ float g_Q[B_*T_*H_*HD_];       // [b*T+t][h*128+d]
__device__ float g_K[B_*T_*KVH_*HD_];     // [b*T+s][kh*128+d]
__device__ float g_V[B_*T_*KVH_*HD_];     // tf32-rounded values (stored fp32)
__device__ float g_Kt[B_*KVH_*HD_*T_];    // [((b*KVH+kh)*128+d)*T + s], tf32-rounded
__device__ float g_O[B_*T_*H_*HD_];

// ==================== mma.sync tf32 helpers (arch-agnostic) ====================
__device__ __forceinline__ uint32_t smem_u32(const void* p) {
    uint32_t a;
    asm("{ .reg .u64 t; cvta.to.shared.u64 t, %1; cvt.u32.u64 %0, t; }"
        : "=r"(a) : "l"(p));
    return a;
}

__device__ __forceinline__ uint32_t f2tf(float f) {
    uint32_t r;
    asm("cvt.rna.tf32.f32 %0, %1;" : "=r"(r) : "f"(f));
    return r;
}

__device__ __forceinline__ void mma_tf32(float* c, const uint32_t* a, const uint32_t* b) {
    asm volatile(
        "mma.sync.aligned.m16n8k8.row.col.f32.tf32.tf32.f32 "
        "{%0,%1,%2,%3}, {%4,%5,%6,%7}, {%8,%9}, {%0,%1,%2,%3};"
        : "+f"(c[0]), "+f"(c[1]), "+f"(c[2]), "+f"(c[3])
        : "r"(a[0]), "r"(a[1]), "r"(a[2]), "r"(a[3]), "r"(b[0]), "r"(b[1]));
}

// ldmatrix x4 on 32-bit data: four 8x4-u32 tiles viewed as 8x8 b16 matrices.
// Lane l supplies the row address: tile = l>>3, row = l&7.
__device__ __forceinline__ void ldm_x4(uint32_t* r, uint32_t addr) {
    asm volatile("ldmatrix.sync.aligned.m8n8.x4.shared.b16 {%0,%1,%2,%3}, [%4];"
                 : "=r"(r[0]), "=r"(r[1]), "=r"(r[2]), "=r"(r[3]) : "r"(addr));
}

#define CPA16(dst, src) \
    asm volatile("cp.async.cg.shared.global [%0], [%1], 16;" \
                 :: "r"(dst), "l"(src) : "memory")
#define CP_COMMIT() asm volatile("cp.async.commit_group;" ::: "memory")
#define CP_WAIT1()  asm volatile("cp.async.wait_group 1;" ::: "memory")
#define CP_WAIT0()  asm volatile("cp.async.wait_group 0;" ::: "memory")

// =====================================================================
// Tensor-core tf32 GEMM:  C[M,N] = A[M,K] @ W[K,N] (+bias)
// 128x128 CTA tile, BK=16, 256 threads (8 warps, 2x4), warp tile 64x32.
// A-fragments via ldmatrix (ASTRIDE=20 u32 rows: 16B-aligned, 8 distinct
// quad-banks -> conflict-free). rnd=1: round output to tf32 (for V).
// =====================================================================
#define ASTRIDE 20
#define BSTRIDE 132

__global__ void __launch_bounds__(256) gemm_mma(
    const float* __restrict__ A, const float* __restrict__ W,
    const float* __restrict__ bias, float* __restrict__ Cout,
    int N, int K, int rnd)
{
    __shared__ __align__(16) uint32_t As[2][128 * ASTRIDE];   // [m][k] tf32
    __shared__ __align__(16) uint32_t Bs[2][16 * BSTRIDE];    // [k][n] tf32

    const int tid  = threadIdx.x;
    const int wid  = tid >> 5;
    const int lane = tid & 31;
    const int g    = lane >> 2;
    const int tg   = lane & 3;
    const int rowBlk = blockIdx.y * 128;
    const int colBlk = blockIdx.x * 128;
    const int warp_m = (wid & 1) * 64;
    const int warp_n = (wid >> 1) * 32;

    // ldmatrix lane address components (A fragments)
    const int lrow = (lane & 7) + ((lane >> 3) & 1) * 8;  // row within 16-row tile
    const int lcol = ((lane >> 4) & 1) * 4;               // k-quad select

    const uint32_t as_base0 = smem_u32(&As[0][0]);
    const uint32_t as_base1 = smem_u32(&As[1][0]);

    float acc[4][4][4];
#pragma unroll
    for (int mt = 0; mt < 4; mt++)
#pragma unroll
        for (int nt = 0; nt < 4; nt++)
#pragma unroll
            for (int i = 0; i < 4; i++) acc[mt][nt][i] = 0.f;

    const int ar  = tid >> 1;
    const int akc = (tid & 1) * 8;
    const int bk  = tid >> 4;
    const int bn  = (tid & 15) * 8;

    const float* Ag = A + (long)(rowBlk + ar) * K + akc;
    const float* Wg = W + (long)bk * N + colBlk + bn;

    const int nit = K / 16;

    {
        float4 a0 = *(const float4*)(Ag);
        float4 a1 = *(const float4*)(Ag + 4);
        float4 b0 = *(const float4*)(Wg);
        float4 b1 = *(const float4*)(Wg + 4);
        uint32_t* ap = &As[0][ar * ASTRIDE + akc];
        ap[0]=f2tf(a0.x); ap[1]=f2tf(a0.y); ap[2]=f2tf(a0.z); ap[3]=f2tf(a0.w);
        ap[4]=f2tf(a1.x); ap[5]=f2tf(a1.y); ap[6]=f2tf(a1.z); ap[7]=f2tf(a1.w);
        uint32_t* bp = &Bs[0][bk * BSTRIDE + bn];
        bp[0]=f2tf(b0.x); bp[1]=f2tf(b0.y); bp[2]=f2tf(b0.z); bp[3]=f2tf(b0.w);
        bp[4]=f2tf(b1.x); bp[5]=f2tf(b1.y); bp[6]=f2tf(b1.z); bp[7]=f2tf(b1.w);
    }
    __syncthreads();

    for (int it = 0; it < nit; it++) {
        const int cur = it & 1;
        const uint32_t as_base = cur ? as_base1 : as_base0;
        float4 pa0, pa1, pb0, pb1;
        if (it + 1 < nit) {
            const float* Agn = Ag + (it + 1) * 16;
            const float* Wgn = Wg + (long)(it + 1) * 16 * N;
            pa0 = *(const float4*)(Agn);
            pa1 = *(const float4*)(Agn + 4);
            pb0 = *(const float4*)(Wgn);
            pb1 = *(const float4*)(Wgn + 4);
        }

#pragma unroll
        for (int ks = 0; ks < 16; ks += 8) {
            uint32_t afr[4][4], bfr[4][2];
#pragma unroll
            for (int mt = 0; mt < 4; mt++) {
                int row = warp_m + mt * 16 + lrow;
                ldm_x4(afr[mt], as_base + (uint32_t)(row * ASTRIDE + ks + lcol) * 4u);
            }
#pragma unroll
            for (int nt = 0; nt < 4; nt++) {
                int brow = ks + tg;
                int bcol = warp_n + nt * 8 + g;
                bfr[nt][0] = Bs[cur][brow * BSTRIDE + bcol];
                bfr[nt][1] = Bs[cur][(brow + 4) * BSTRIDE + bcol];
            }
#pragma unroll
            for (int mt = 0; mt < 4; mt++)
#pragma unroll
                for (int nt = 0; nt < 4; nt++)
                    mma_tf32(acc[mt][nt], afr[mt], bfr[nt]);
        }
        __syncthreads();

        if (it + 1 < nit) {
            const int nxt = cur ^ 1;
            uint32_t* ap = &As[nxt][ar * ASTRIDE + akc];
            ap[0]=f2tf(pa0.x); ap[1]=f2tf(pa0.y); ap[2]=f2tf(pa0.z); ap[3]=f2tf(pa0.w);
            ap[4]=f2tf(pa1.x); ap[5]=f2tf(pa1.y); ap[6]=f2tf(pa1.z); ap[7]=f2tf(pa1.w);
            uint32_t* bp = &Bs[nxt][bk * BSTRIDE + bn];
            bp[0]=f2tf(pb0.x); bp[1]=f2tf(pb0.y); bp[2]=f2tf(pb0.z); bp[3]=f2tf(pb0.w);
            bp[4]=f2tf(pb1.x); bp[5]=f2tf(pb1.y); bp[6]=f2tf(pb1.z); bp[7]=f2tf(pb1.w);
            __syncthreads();
        }
    }

#pragma unroll
    for (int mt = 0; mt < 4; mt++) {
        int row = rowBlk + warp_m + mt * 16 + g;
#pragma unroll
        for (int nt = 0; nt < 4; nt++) {
            int col = colBlk + warp_n + nt * 8 + 2 * tg;
            float b0 = 0.f, b1 = 0.f;
            if (bias) { b0 = bias[col]; b1 = bias[col + 1]; }
            float v0 = acc[mt][nt][0] + b0, v1 = acc[mt][nt][1] + b1;
            float v2 = acc[mt][nt][2] + b0, v3 = acc[mt][nt][3] + b1;
            if (rnd) {   // round to tf32 so downstream HW-truncation is exact
                v0 = __uint_as_float(f2tf(v0)); v1 = __uint_as_float(f2tf(v1));
                v2 = __uint_as_float(f2tf(v2)); v3 = __uint_as_float(f2tf(v3));
            }
            float* c0 = Cout + (long)row * N + col;
            float* c1 = Cout + (long)(row + 8) * N + col;
            *(float2*)c0 = make_float2(v0, v1);
            *(float2*)c1 = make_float2(v2, v3);
        }
    }
}

// =====================================================================
// RoPE on Q, in place.
// =====================================================================
__global__ void __launch_bounds__(256) rope_q_kernel()
{
    int idx = blockIdx.x * 256 + threadIdx.x;
    int d  = idx & 63;
    int rh = idx >> 6;
    int h  = rh & (H_ - 1);
    int bt = rh >> 4;
    int t  = bt & (T_ - 1);
    long base = (long)bt * (H_*HD_) + h * HD_;
    float invf = expf(-(float)d * (9.210340371976184f / 64.0f));
    float sn, cs;
    sincosf((float)t * invf, &sn, &cs);
    float x1 = g_Q[base + d];
    float x2 = g_Q[base + d + 64];
    g_Q[base + d]      = x1 * cs - x2 * sn;
    g_Q[base + d + 64] = x2 * cs + x1 * sn;
}

// =====================================================================
// RoPE on K + transpose to [B,KVH,HD,T]; output tf32-ROUNDED (unbiased)
// so flash's cp.async -> HW truncation is exact.
// =====================================================================
__global__ void __launch_bounds__(256) ropeT_k_kernel()
{
    __shared__ float sm1[32][33];
    __shared__ float sm2[32][33];
    const int tid = threadIdx.x;
    const int s0  = blockIdx.x * 32;
    const int d0  = blockIdx.y * 32;
    const int bkh = blockIdx.z;
    const int b   = bkh >> 2;
    const int kh  = bkh & 3;

    {
        int r  = tid >> 3;
        int c4 = (tid & 7) * 4;
        long gbase = (long)(b*T_ + s0 + r) * (KVH_*HD_) + kh * HD_;
        float4 v1 = *(const float4*)(g_K + gbase + d0 + c4);
        float4 v2 = *(const float4*)(g_K + gbase + d0 + 64 + c4);
        sm1[r][c4+0]=v1.x; sm1[r][c4+1]=v1.y; sm1[r][c4+2]=v1.z; sm1[r][c4+3]=v1.w;
        sm2[r][c4+0]=v2.x; sm2[r][c4+1]=v2.y; sm2[r][c4+2]=v2.z; sm2[r][c4+3]=v2.w;
    }
    __syncthreads();

    const int dl = tid >> 2;
    const int cg = tid & 3;
    const int dd = dl & 31;
    float invf = expf(-(float)(d0 + dd) * (9.210340371976184f / 64.0f));
    int dglob = (dl < 32) ? (d0 + dd) : (64 + d0 + dd);
    long obase = (long)(bkh * HD_ + dglob) * T_;
#pragma unroll
    for (int i = 0; i < 8; i++) {
        int cc = cg * 8 + i;
        int t  = s0 + cc;
        float sn, cs;
        sincosf((float)t * invf, &sn, &cs);
        float x1 = sm1[cc][dd];
        float x2 = sm2[cc][dd];
        float out = (dl < 32) ? (x1 * cs - x2 * sn) : (x2 * cs + x1 * sn);
        g_Kt[obase + t] = __uint_as_float(f2tf(out));
    }
}

// =====================================================================
// Tensor-core flash attention (causal, GQA).
// BM=128, BN=64, 256 threads (8 warps x 16 rows). tf32 mma for S and PV.
// Q fragments via ldmatrix (FQS=132 rows: 16B-aligned, conflict-free).
// K/V tiles streamed via cp.async (pre-rounded tf32 values).
// =====================================================================
#define FQS 132
#define FKS 68
#define FVS 132
#define KOFF 67584                 // 128*132*4
#define KSZ  34816                 // 128*68*4
#define VOFF (KOFF + 2*KSZ)        // 137216
#define VSZ  33792                 // 64*132*4
#define FLASH_SMEM (VOFF + 2*VSZ)  // 204800

__global__ void __launch_bounds__(256) flash_tc()
{
    extern __shared__ char smem[];
    uint32_t* Qs  = (uint32_t*)smem;
    const uint32_t sb = smem_u32(smem);

    const int tid = threadIdx.x;
    const int qt  = blockIdx.x;
    const int h   = blockIdx.y;
    const int b   = blockIdx.z;
    const int kh  = h >> 2;
    const int t0  = qt * 128;
    const int wm  = (tid >> 5) * 16;
    const int lane = tid & 31;
    const int g = lane >> 2, tg = lane & 3;

    // ldmatrix lane address components (Q fragments)
    const int lrow = (lane & 7) + ((lane >> 3) & 1) * 8;
    const int lcol = ((lane >> 4) & 1) * 4;

    const float* kg = g_Kt + (long)(b*KVH_ + kh) * HD_ * T_;   // [d][s]
    const float* vg = g_V  + (long)b*T_*(KVH_*HD_) + kh*HD_;   // [s][d]
    const float scale = 0.08838834764831845f;                  // 1/sqrt(128)

    // ---- Q tile: LDG -> scale -> tf32(round) -> smem ----
    {
        const float* qg = g_Q + (long)(b*T_ + t0) * (H_*HD_) + h*HD_;
#pragma unroll
        for (int it = 0; it < 16; it++) {
            int idx = tid + it*256;
            int r = idx >> 5, d4 = (idx & 31) * 4;
            float4 v = *(const float4*)(qg + (long)r*(H_*HD_) + d4);
            uint32_t* qp = &Qs[r*FQS + d4];
            qp[0] = f2tf(v.x * scale); qp[1] = f2tf(v.y * scale);
            qp[2] = f2tf(v.z * scale); qp[3] = f2tf(v.w * scale);
        }
    }

    const int nkt = 2*qt + 2;

    // ---- prologue: cp.async tile 0 into buffer 0 ----
    {
        const int s0n = 0;
#pragma unroll
        for (int it = 0; it < 8; it++) {
            int idx = tid + it*256;
            int d = idx >> 4, c4 = (idx & 15) * 4;
            CPA16(sb + KOFF + (d*FKS + c4)*4, (const void*)(kg + (long)d*T_ + s0n + c4));
        }
#pragma unroll
        for (int it = 0; it < 8; it++) {
            int idx = tid + it*256;
            int c = idx >> 5, d4 = (idx & 31) * 4;
            CPA16(sb + VOFF + (c*FVS + d4)*4, (const void*)(vg + (long)(s0n + c)*(KVH_*HD_) + d4));
        }
        CP_COMMIT();
    }

    float o[16][4];
#pragma unroll
    for (int nt = 0; nt < 16; nt++)
#pragma unroll
        for (int i = 0; i < 4; i++) o[nt][i] = 0.f;
    float m0 = -1e30f, m1 = -1e30f, l0 = 0.f, l1 = 0.f;

    for (int kt = 0; kt < nkt; kt++) {
        const int cur = kt & 1;
        if (kt + 1 < nkt) {
            const int s0n = (kt + 1) * 64;
            const int sel = cur ^ 1;
#pragma unroll
            for (int it = 0; it < 8; it++) {
                int idx = tid + it*256;
                int d = idx >> 4, c4 = (idx & 15) * 4;
                CPA16(sb + KOFF + sel*KSZ + (d*FKS + c4)*4,
                      (const void*)(kg + (long)d*T_ + s0n + c4));
            }
#pragma unroll
            for (int it = 0; it < 8; it++) {
                int idx = tid + it*256;
                int c = idx >> 5, d4 = (idx & 31) * 4;
                CPA16(sb + VOFF + sel*VSZ + (c*FVS + d4)*4,
                      (const void*)(vg + (long)(s0n + c)*(KVH_*HD_) + d4));
            }
            CP_COMMIT();
            CP_WAIT1();
        } else {
            CP_WAIT0();
        }
        __syncthreads();

        const uint32_t* Kc = (const uint32_t*)(smem + KOFF + cur*KSZ);
        const uint32_t* Vc = (const uint32_t*)(smem + VOFF + cur*VSZ);

        // ---- S = Q @ K^T (scaled; tf32 mma, Q frags via ldmatrix) ----
        float sf[8][4];
#pragma unroll
        for (int nt = 0; nt < 8; nt++)
#pragma unroll
            for (int i = 0; i < 4; i++) sf[nt][i] = 0.f;

#pragma unroll
        for (int kd = 0; kd < 16; kd++) {
            uint32_t a[4];
            ldm_x4(a, sb + (uint32_t)((wm + lrow)*FQS + kd*8 + lcol) * 4u);
#pragma unroll
            for (int nt = 0; nt < 8; nt++) {
                uint32_t bb[2];
                bb[0] = Kc[(kd*8+tg)*FKS   + nt*8 + g];
                bb[1] = Kc[(kd*8+tg+4)*FKS + nt*8 + g];
                mma_tf32(sf[nt], a, bb);
            }
        }

        // ---- causal mask (only the two diagonal tiles) ----
        if (kt >= nkt - 2) {
            const int s0c = kt * 64;
            const int r0 = t0 + wm + g, r1 = r0 + 8;
#pragma unroll
            for (int nt = 0; nt < 8; nt++) {
                int c0 = s0c + nt*8 + 2*tg;
                if (c0     > r0) sf[nt][0] = -1e30f;
                if (c0 + 1 > r0) sf[nt][1] = -1e30f;
                if (c0     > r1) sf[nt][2] = -1e30f;
                if (c0 + 1 > r1) sf[nt][3] = -1e30f;
            }
        }

        // ---- online softmax (registers only; rows g and g+8) ----
        float mt0 = -1e30f, mt1 = -1e30f;
#pragma unroll
        for (int nt = 0; nt < 8; nt++) {
            mt0 = fmaxf(mt0, fmaxf(sf[nt][0], sf[nt][1]));
            mt1 = fmaxf(mt1, fmaxf(sf[nt][2], sf[nt][3]));
        }
        mt0 = fmaxf(mt0, __shfl_xor_sync(0xffffffffu, mt0, 1));
        mt0 = fmaxf(mt0, __shfl_xor_sync(0xffffffffu, mt0, 2));
        mt1 = fmaxf(mt1, __shfl_xor_sync(0xffffffffu, mt1, 1));
        mt1 = fmaxf(mt1, __shfl_xor_sync(0xffffffffu, mt1, 2));

        float mn0 = fmaxf(m0, mt0), mn1 = fmaxf(m1, mt1);
        float al0 = __expf(m0 - mn0), al1 = __expf(m1 - mn1);
        m0 = mn0; m1 = mn1;

        float rs0 = 0.f, rs1 = 0.f;
        uint32_t pf[8][4];
#pragma unroll
        for (int nt = 0; nt < 8; nt++) {
            float p0 = __expf(sf[nt][0] - mn0);
            float p1 = __expf(sf[nt][1] - mn0);
            float p2 = __expf(sf[nt][2] - mn1);
            float p3 = __expf(sf[nt][3] - mn1);
            rs0 += p0 + p1; rs1 += p2 + p3;
            pf[nt][0] = f2tf(p0); pf[nt][1] = f2tf(p1);
            pf[nt][2] = f2tf(p2); pf[nt][3] = f2tf(p3);
        }
        rs0 += __shfl_xor_sync(0xffffffffu, rs0, 1);
        rs0 += __shfl_xor_sync(0xffffffffu, rs0, 2);
        rs1 += __shfl_xor_sync(0xffffffffu, rs1, 1);
        rs1 += __shfl_xor_sync(0xffffffffu, rs1, 2);
        l0 = l0 * al0 + rs0;
        l1 = l1 * al1 + rs1;

#pragma unroll
        for (int nt = 0; nt < 16; nt++) {
            o[nt][0] *= al0; o[nt][1] *= al0;
            o[nt][2] *= al1; o[nt][3] *= al1;
        }

        // ---- O += P @ V (A-fragments from pf via intra-warp shuffles) ----
#pragma unroll
        for (int ks = 0; ks < 8; ks++) {
            const int src1 = (g << 2) | (tg >> 1);
            uint32_t u0 = __shfl_sync(0xffffffffu, pf[ks][0], src1);
            uint32_t u1 = __shfl_sync(0xffffffffu, pf[ks][1], src1);
            uint32_t u2 = __shfl_sync(0xffffffffu, pf[ks][2], src1);
            uint32_t u3 = __shfl_sync(0xffffffffu, pf[ks][3], src1);
            uint32_t w0 = __shfl_sync(0xffffffffu, pf[ks][0], src1 + 2);
            uint32_t w1 = __shfl_sync(0xffffffffu, pf[ks][1], src1 + 2);
            uint32_t w2 = __shfl_sync(0xffffffffu, pf[ks][2], src1 + 2);
            uint32_t w3 = __shfl_sync(0xffffffffu, pf[ks][3], src1 + 2);
            uint32_t a[4];
            a[0] = (tg & 1) ? u1 : u0;
            a[1] = (tg & 1) ? u3 : u2;
            a[2] = (tg & 1) ? w1 : w0;
            a[3] = (tg & 1) ? w3 : w2;
#pragma unroll
            for (int nt = 0; nt < 16; nt++) {
                uint32_t bb[2];
                bb[0] = Vc[(ks*8+tg)*FVS   + nt*8 + g];
                bb[1] = Vc[(ks*8+tg+4)*FVS + nt*8 + g];
                mma_tf32(o[nt], a, bb);
            }
        }
        __syncthreads();
    }

    // ---- epilogue: normalize and store ----
    const float inv0 = 1.0f / l0, inv1 = 1.0f / l1;
    float* og0 = g_O + (long)(b*T_ + t0 + wm + g) * (H_*HD_) + h*HD_;
    float* og1 = og0 + 8L * (H_*HD_);
#pragma unroll
    for (int nt = 0; nt < 16; nt++) {
        int c = nt*8 + 2*tg;
        *(float2*)(og0 + c) = make_float2(o[nt][0]*inv0, o[nt][1]*inv0);
        *(float2*)(og1 + c) = make_float2(o[nt][2]*inv1, o[nt][3]*inv1);
    }
}

// =====================================================================
// host launcher
// =====================================================================
extern "C" void kernel_launch(void* const* d_in, const int* in_sizes, int n_in,
                              void* d_out, int out_size)
{
    const float* x  = (const float*)d_in[0];
    const float* wq = (const float*)d_in[1];
    const float* bq = (const float*)d_in[2];
    const float* wk = (const float*)d_in[3];
    const float* bk = (const float*)d_in[4];
    const float* wv = (const float*)d_in[5];
    const float* bv = (const float*)d_in[6];
    const float* wo = (const float*)d_in[7];
    float* out = (float*)d_out;

    float *qp, *kp, *vp, *op;
    cudaGetSymbolAddress((void**)&qp, g_Q);
    cudaGetSymbolAddress((void**)&kp, g_K);
    cudaGetSymbolAddress((void**)&vp, g_V);
    cudaGetSymbolAddress((void**)&op, g_O);

    cudaFuncSetAttribute(flash_tc,
                         cudaFuncAttributeMaxDynamicSharedMemorySize, FLASH_SMEM);

    dim3 blk(256);

    // QKV projections (tf32 mma.sync); V output rounded to tf32
    gemm_mma<<<dim3((H_*HD_)/128,   MROWS/128), blk>>>(x, wq, bq, qp, H_*HD_,   C_, 0);
    gemm_mma<<<dim3((KVH_*HD_)/128, MROWS/128), blk>>>(x, wk, bk, kp, KVH_*HD_, C_, 0);
    gemm_mma<<<dim3((KVH_*HD_)/128, MROWS/128), blk>>>(x, wv, bv, vp, KVH_*HD_, C_, 1);

    // RoPE (K output tf32-rounded)
    rope_q_kernel<<<(B_*T_*H_*64)/256, blk>>>();
    ropeT_k_kernel<<<dim3(T_/32, 2, B_*KVH_), blk>>>();

    // tensor-core flash attention
    flash_tc<<<dim3(T_/128, H_, B_), blk, FLASH_SMEM>>>();

    // output projection (tf32 mma.sync)
    gemm_mma<<<dim3(C_/128, MROWS/128), blk>>>(op, wo, nullptr, out, C_, H_*HD_, 0);
}

// round 8
// speedup vs baseline: 1.8515x; 1.8515x over previous
#include <cuda_runtime.h>
#include <math.h>
#include <stdint.h>

#define B_   2
#define T_   2048
#define C_   2048
#define H_   16
#define KVH_ 4
#define HD_  128
#define MROWS (B_*T_)   // 4096

// ---------------- scratch (device globals; no allocations) ----------------
__device__ float g_Q[B_*T_*H_*HD_];       // [b*T+t][h*128+d]
__device__ float g_K[B_*T_*KVH_*HD_];     // [b*T+s][kh*128+d]
__device__ float g_V[B_*T_*KVH_*HD_];     // tf32-rounded (stored fp32)
__device__ float g_Kt[B_*KVH_*HD_*T_];    // [((b*KVH+kh)*128+d)*T + s], tf32-rounded
__device__ float g_O[B_*T_*H_*HD_];       // tf32-rounded (stored fp32)
// pre-rounded tf32 copies of GEMM operands
__device__ float g_Xr[B_*T_*C_];          // 32MB
__device__ float g_Wq[C_*H_*HD_];         // 16MB
__device__ float g_Wk[C_*KVH_*HD_];       //  4MB
__device__ float g_Wv[C_*KVH_*HD_];       //  4MB
__device__ float g_Wo[H_*HD_*C_];         // 16MB

// ==================== helpers ====================
__device__ __forceinline__ uint32_t smem_u32(const void* p) {
    uint32_t a;
    asm("{ .reg .u64 t; cvta.to.shared.u64 t, %1; cvt.u32.u64 %0, t; }"
        : "=r"(a) : "l"(p));
    return a;
}

__device__ __forceinline__ uint32_t f2tf(float f) {
    uint32_t r;
    asm("cvt.rna.tf32.f32 %0, %1;" : "=r"(r) : "f"(f));
    return r;
}

__device__ __forceinline__ void mma_tf32(float* c, const uint32_t* a, const uint32_t* b) {
    asm volatile(
        "mma.sync.aligned.m16n8k8.row.col.f32.tf32.tf32.f32 "
        "{%0,%1,%2,%3}, {%4,%5,%6,%7}, {%8,%9}, {%0,%1,%2,%3};"
        : "+f"(c[0]), "+f"(c[1]), "+f"(c[2]), "+f"(c[3])
        : "r"(a[0]), "r"(a[1]), "r"(a[2]), "r"(a[3]), "r"(b[0]), "r"(b[1]));
}

#define CPA16(dst, src) \
    asm volatile("cp.async.cg.shared.global [%0], [%1], 16;" \
                 :: "r"(dst), "l"(src) : "memory")
#define CP_COMMIT() asm volatile("cp.async.commit_group;" ::: "memory")
#define CP_WAIT1()  asm volatile("cp.async.wait_group 1;" ::: "memory")
#define CP_WAIT0()  asm volatile("cp.async.wait_group 0;" ::: "memory")

// =====================================================================
// Pre-round fp32 -> tf32-rounded fp32 (vectorized elementwise)
// =====================================================================
__global__ void __launch_bounds__(256) round_tf32_kernel(
    const float* __restrict__ src, float* __restrict__ dst, int n4)
{
    int i = blockIdx.x * 256 + threadIdx.x;
    if (i < n4) {
        float4 v = *(const float4*)(src + (long)i * 4);
        v.x = __uint_as_float(f2tf(v.x));
        v.y = __uint_as_float(f2tf(v.y));
        v.z = __uint_as_float(f2tf(v.z));
        v.w = __uint_as_float(f2tf(v.w));
        *(float4*)(dst + (long)i * 4) = v;
    }
}

// =====================================================================
// Tensor-core tf32 GEMM:  C[M,N] = A[M,K] @ W[K,N] (+bias)
// A/W must be tf32-rounded fp32 (cp.async -> HW truncation is exact).
// 128x128 CTA tile, BK=16, 256 threads (8 warps 2x4), warp tile 64x32.
// cp.async double-buffered tiles; scalar-LDS fragments (R6 proven path).
// =====================================================================
#define ASTRIDE 20
#define BSTRIDE 132
#define GA_SZ (128*ASTRIDE*4)   // bytes per A buffer
#define GB_SZ (16*BSTRIDE*4)    // bytes per B buffer

__global__ void __launch_bounds__(256) gemm_mma(
    const float* __restrict__ A, const float* __restrict__ W,
    const float* __restrict__ bias, float* __restrict__ Cout,
    int N, int K, int rnd)
{
    __shared__ __align__(16) uint32_t As[2][128 * ASTRIDE];   // [m][k]
    __shared__ __align__(16) uint32_t Bs[2][16 * BSTRIDE];    // [k][n]

    const int tid  = threadIdx.x;
    const int wid  = tid >> 5;
    const int lane = tid & 31;
    const int g    = lane >> 2;
    const int tg   = lane & 3;
    const int rowBlk = blockIdx.y * 128;
    const int colBlk = blockIdx.x * 128;
    const int warp_m = (wid & 1) * 64;
    const int warp_n = (wid >> 1) * 32;

    const uint32_t sbA = smem_u32(&As[0][0]);
    const uint32_t sbB = smem_u32(&Bs[0][0]);

    float acc[4][4][4];
#pragma unroll
    for (int mt = 0; mt < 4; mt++)
#pragma unroll
        for (int nt = 0; nt < 4; nt++)
#pragma unroll
            for (int i = 0; i < 4; i++) acc[mt][nt][i] = 0.f;

    // cp.async loader mapping: A tile 512 chunks, B tile 512 chunks
    const int a_r  = tid >> 2;            // with idx=tid+i*256: r = idx>>2
    const int a_c4 = (tid & 3) * 4;
    const int b_k  = tid >> 5;
    const int b_n4 = (tid & 31) * 4;

    const int nit = K / 16;

    // ---- prologue: tile 0 -> buffer 0 ----
    {
#pragma unroll
        for (int i = 0; i < 2; i++) {
            int idx = tid + i * 256;
            int r = idx >> 2, c4 = (idx & 3) * 4;
            CPA16(sbA + (uint32_t)(r * ASTRIDE + c4) * 4u,
                  (const void*)(A + (long)(rowBlk + r) * K + c4));
        }
#pragma unroll
        for (int i = 0; i < 2; i++) {
            int idx = tid + i * 256;
            int k = idx >> 5, n4 = (idx & 31) * 4;
            CPA16(sbB + (uint32_t)(k * BSTRIDE + n4) * 4u,
                  (const void*)(W + (long)k * N + colBlk + n4));
        }
        CP_COMMIT();
    }

    for (int it = 0; it < nit; it++) {
        const int cur = it & 1;
        if (it + 1 < nit) {
            const int sel = cur ^ 1;
            const int k0 = (it + 1) * 16;
#pragma unroll
            for (int i = 0; i < 2; i++) {
                int idx = tid + i * 256;
                int r = idx >> 2, c4 = (idx & 3) * 4;
                CPA16(sbA + (uint32_t)(sel * GA_SZ) + (uint32_t)(r * ASTRIDE + c4) * 4u,
                      (const void*)(A + (long)(rowBlk + r) * K + k0 + c4));
            }
#pragma unroll
            for (int i = 0; i < 2; i++) {
                int idx = tid + i * 256;
                int k = idx >> 5, n4 = (idx & 31) * 4;
                CPA16(sbB + (uint32_t)(sel * GB_SZ) + (uint32_t)(k * BSTRIDE + n4) * 4u,
                      (const void*)(W + (long)(k0 + k) * N + colBlk + n4));
            }
            CP_COMMIT();
            CP_WAIT1();
        } else {
            CP_WAIT0();
        }
        __syncthreads();

#pragma unroll
        for (int ks = 0; ks < 16; ks += 8) {
            uint32_t afr[4][4], bfr[4][2];
#pragma unroll
            for (int mt = 0; mt < 4; mt++) {
                int arow = warp_m + mt * 16 + g;
                int acol = ks + tg;
                afr[mt][0] = As[cur][arow * ASTRIDE + acol];
                afr[mt][1] = As[cur][(arow + 8) * ASTRIDE + acol];
                afr[mt][2] = As[cur][arow * ASTRIDE + acol + 4];
                afr[mt][3] = As[cur][(arow + 8) * ASTRIDE + acol + 4];
            }
#pragma unroll
            for (int nt = 0; nt < 4; nt++) {
                int brow = ks + tg;
                int bcol = warp_n + nt * 8 + g;
                bfr[nt][0] = Bs[cur][brow * BSTRIDE + bcol];
                bfr[nt][1] = Bs[cur][(brow + 4) * BSTRIDE + bcol];
            }
#pragma unroll
            for (int mt = 0; mt < 4; mt++)
#pragma unroll
                for (int nt = 0; nt < 4; nt++)
                    mma_tf32(acc[mt][nt], afr[mt], bfr[nt]);
        }
        __syncthreads();
    }

#pragma unroll
    for (int mt = 0; mt < 4; mt++) {
        int row = rowBlk + warp_m + mt * 16 + g;
#pragma unroll
        for (int nt = 0; nt < 4; nt++) {
            int col = colBlk + warp_n + nt * 8 + 2 * tg;
            float b0 = 0.f, b1 = 0.f;
            if (bias) { b0 = bias[col]; b1 = bias[col + 1]; }
            float v0 = acc[mt][nt][0] + b0, v1 = acc[mt][nt][1] + b1;
            float v2 = acc[mt][nt][2] + b0, v3 = acc[mt][nt][3] + b1;
            if (rnd) {
                v0 = __uint_as_float(f2tf(v0)); v1 = __uint_as_float(f2tf(v1));
                v2 = __uint_as_float(f2tf(v2)); v3 = __uint_as_float(f2tf(v3));
            }
            float* c0 = Cout + (long)row * N + col;
            float* c1 = Cout + (long)(row + 8) * N + col;
            *(float2*)c0 = make_float2(v0, v1);
            *(float2*)c1 = make_float2(v2, v3);
        }
    }
}

// =====================================================================
// RoPE on Q, in place.
// =====================================================================
__global__ void __launch_bounds__(256) rope_q_kernel()
{
    int idx = blockIdx.x * 256 + threadIdx.x;
    int d  = idx & 63;
    int rh = idx >> 6;
    int h  = rh & (H_ - 1);
    int bt = rh >> 4;
    int t  = bt & (T_ - 1);
    long base = (long)bt * (H_*HD_) + h * HD_;
    float invf = expf(-(float)d * (9.210340371976184f / 64.0f));
    float sn, cs;
    sincosf((float)t * invf, &sn, &cs);
    float x1 = g_Q[base + d];
    float x2 = g_Q[base + d + 64];
    g_Q[base + d]      = x1 * cs - x2 * sn;
    g_Q[base + d + 64] = x2 * cs + x1 * sn;
}

// =====================================================================
// RoPE on K + transpose to [B,KVH,HD,T]; output tf32-ROUNDED.
// =====================================================================
__global__ void __launch_bounds__(256) ropeT_k_kernel()
{
    __shared__ float sm1[32][33];
    __shared__ float sm2[32][33];
    const int tid = threadIdx.x;
    const int s0  = blockIdx.x * 32;
    const int d0  = blockIdx.y * 32;
    const int bkh = blockIdx.z;
    const int b   = bkh >> 2;
    const int kh  = bkh & 3;

    {
        int r  = tid >> 3;
        int c4 = (tid & 7) * 4;
        long gbase = (long)(b*T_ + s0 + r) * (KVH_*HD_) + kh * HD_;
        float4 v1 = *(const float4*)(g_K + gbase + d0 + c4);
        float4 v2 = *(const float4*)(g_K + gbase + d0 + 64 + c4);
        sm1[r][c4+0]=v1.x; sm1[r][c4+1]=v1.y; sm1[r][c4+2]=v1.z; sm1[r][c4+3]=v1.w;
        sm2[r][c4+0]=v2.x; sm2[r][c4+1]=v2.y; sm2[r][c4+2]=v2.z; sm2[r][c4+3]=v2.w;
    }
    __syncthreads();

    const int dl = tid >> 2;
    const int cg = tid & 3;
    const int dd = dl & 31;
    float invf = expf(-(float)(d0 + dd) * (9.210340371976184f / 64.0f));
    int dglob = (dl < 32) ? (d0 + dd) : (64 + d0 + dd);
    long obase = (long)(bkh * HD_ + dglob) * T_;
#pragma unroll
    for (int i = 0; i < 8; i++) {
        int cc = cg * 8 + i;
        int t  = s0 + cc;
        float sn, cs;
        sincosf((float)t * invf, &sn, &cs);
        float x1 = sm1[cc][dd];
        float x2 = sm2[cc][dd];
        float out = (dl < 32) ? (x1 * cs - x2 * sn) : (x2 * cs + x1 * sn);
        g_Kt[obase + t] = __uint_as_float(f2tf(out));
    }
}

// =====================================================================
// Tensor-core flash attention (causal, GQA).  (R6 proven structure)
// BM=128, BN=64, 256 threads (8 warps x 16 rows). tf32 mma for S and PV.
// =====================================================================
#define FQS 132
#define FKS 68
#define FVS 132
#define KOFF 67584                 // 128*132*4
#define KSZ  34816                 // 128*68*4
#define VOFF (KOFF + 2*KSZ)        // 137216
#define VSZ  33792                 // 64*132*4
#define FLASH_SMEM (VOFF + 2*VSZ)  // 204800

__global__ void __launch_bounds__(256) flash_tc()
{
    extern __shared__ char smem[];
    uint32_t* Qs  = (uint32_t*)smem;
    const uint32_t sb = smem_u32(smem);

    const int tid = threadIdx.x;
    const int qt  = blockIdx.x;
    const int h   = blockIdx.y;
    const int b   = blockIdx.z;
    const int kh  = h >> 2;
    const int t0  = qt * 128;
    const int wm  = (tid >> 5) * 16;
    const int lane = tid & 31;
    const int g = lane >> 2, tg = lane & 3;

    const float* kg = g_Kt + (long)(b*KVH_ + kh) * HD_ * T_;   // [d][s]
    const float* vg = g_V  + (long)b*T_*(KVH_*HD_) + kh*HD_;   // [s][d]
    const float scale = 0.08838834764831845f;                  // 1/sqrt(128)

    // ---- Q tile: LDG -> scale -> tf32(round) -> smem ----
    {
        const float* qg = g_Q + (long)(b*T_ + t0) * (H_*HD_) + h*HD_;
#pragma unroll
        for (int it = 0; it < 16; it++) {
            int idx = tid + it*256;
            int r = idx >> 5, d4 = (idx & 31) * 4;
            float4 v = *(const float4*)(qg + (long)r*(H_*HD_) + d4);
            uint32_t* qp = &Qs[r*FQS + d4];
            qp[0] = f2tf(v.x * scale); qp[1] = f2tf(v.y * scale);
            qp[2] = f2tf(v.z * scale); qp[3] = f2tf(v.w * scale);
        }
    }

    const int nkt = 2*qt + 2;

    // ---- prologue: cp.async tile 0 into buffer 0 ----
    {
        const int s0n = 0;
#pragma unroll
        for (int it = 0; it < 8; it++) {
            int idx = tid + it*256;
            int d = idx >> 4, c4 = (idx & 15) * 4;
            CPA16(sb + KOFF + (d*FKS + c4)*4, (const void*)(kg + (long)d*T_ + s0n + c4));
        }
#pragma unroll
        for (int it = 0; it < 8; it++) {
            int idx = tid + it*256;
            int c = idx >> 5, d4 = (idx & 31) * 4;
            CPA16(sb + VOFF + (c*FVS + d4)*4, (const void*)(vg + (long)(s0n + c)*(KVH_*HD_) + d4));
        }
        CP_COMMIT();
    }

    float o[16][4];
#pragma unroll
    for (int nt = 0; nt < 16; nt++)
#pragma unroll
        for (int i = 0; i < 4; i++) o[nt][i] = 0.f;
    float m0 = -1e30f, m1 = -1e30f, l0 = 0.f, l1 = 0.f;

    for (int kt = 0; kt < nkt; kt++) {
        const int cur = kt & 1;
        if (kt + 1 < nkt) {
            const int s0n = (kt + 1) * 64;
            const int sel = cur ^ 1;
#pragma unroll
            for (int it = 0; it < 8; it++) {
                int idx = tid + it*256;
                int d = idx >> 4, c4 = (idx & 15) * 4;
                CPA16(sb + KOFF + sel*KSZ + (d*FKS + c4)*4,
                      (const void*)(kg + (long)d*T_ + s0n + c4));
            }
#pragma unroll
            for (int it = 0; it < 8; it++) {
                int idx = tid + it*256;
                int c = idx >> 5, d4 = (idx & 31) * 4;
                CPA16(sb + VOFF + sel*VSZ + (c*FVS + d4)*4,
                      (const void*)(vg + (long)(s0n + c)*(KVH_*HD_) + d4));
            }
            CP_COMMIT();
            CP_WAIT1();
        } else {
            CP_WAIT0();
        }
        __syncthreads();

        const uint32_t* Kc = (const uint32_t*)(smem + KOFF + cur*KSZ);
        const uint32_t* Vc = (const uint32_t*)(smem + VOFF + cur*VSZ);

        // ---- S = Q @ K^T ----
        float sf[8][4];
#pragma unroll
        for (int nt = 0; nt < 8; nt++)
#pragma unroll
            for (int i = 0; i < 4; i++) sf[nt][i] = 0.f;

#pragma unroll
        for (int kd = 0; kd < 16; kd++) {
            uint32_t a[4];
            a[0] = Qs[(wm+g)*FQS   + kd*8 + tg];
            a[1] = Qs[(wm+g+8)*FQS + kd*8 + tg];
            a[2] = Qs[(wm+g)*FQS   + kd*8 + tg + 4];
            a[3] = Qs[(wm+g+8)*FQS + kd*8 + tg + 4];
#pragma unroll
            for (int nt = 0; nt < 8; nt++) {
                uint32_t bb[2];
                bb[0] = Kc[(kd*8+tg)*FKS   + nt*8 + g];
                bb[1] = Kc[(kd*8+tg+4)*FKS + nt*8 + g];
                mma_tf32(sf[nt], a, bb);
            }
        }

        // ---- causal mask (diagonal tiles only) ----
        if (kt >= nkt - 2) {
            const int s0c = kt * 64;
            const int r0 = t0 + wm + g, r1 = r0 + 8;
#pragma unroll
            for (int nt = 0; nt < 8; nt++) {
                int c0 = s0c + nt*8 + 2*tg;
                if (c0     > r0) sf[nt][0] = -1e30f;
                if (c0 + 1 > r0) sf[nt][1] = -1e30f;
                if (c0     > r1) sf[nt][2] = -1e30f;
                if (c0 + 1 > r1) sf[nt][3] = -1e30f;
            }
        }

        // ---- online softmax (registers only) ----
        float mt0 = -1e30f, mt1 = -1e30f;
#pragma unroll
        for (int nt = 0; nt < 8; nt++) {
            mt0 = fmaxf(mt0, fmaxf(sf[nt][0], sf[nt][1]));
            mt1 = fmaxf(mt1, fmaxf(sf[nt][2], sf[nt][3]));
        }
        mt0 = fmaxf(mt0, __shfl_xor_sync(0xffffffffu, mt0, 1));
        mt0 = fmaxf(mt0, __shfl_xor_sync(0xffffffffu, mt0, 2));
        mt1 = fmaxf(mt1, __shfl_xor_sync(0xffffffffu, mt1, 1));
        mt1 = fmaxf(mt1, __shfl_xor_sync(0xffffffffu, mt1, 2));

        float mn0 = fmaxf(m0, mt0), mn1 = fmaxf(m1, mt1);
        float al0 = __expf(m0 - mn0), al1 = __expf(m1 - mn1);
        m0 = mn0; m1 = mn1;

        float rs0 = 0.f, rs1 = 0.f;
        uint32_t pf[8][4];
#pragma unroll
        for (int nt = 0; nt < 8; nt++) {
            float p0 = __expf(sf[nt][0] - mn0);
            float p1 = __expf(sf[nt][1] - mn0);
            float p2 = __expf(sf[nt][2] - mn1);
            float p3 = __expf(sf[nt][3] - mn1);
            rs0 += p0 + p1; rs1 += p2 + p3;
            pf[nt][0] = f2tf(p0); pf[nt][1] = f2tf(p1);
            pf[nt][2] = f2tf(p2); pf[nt][3] = f2tf(p3);
        }
        rs0 += __shfl_xor_sync(0xffffffffu, rs0, 1);
        rs0 += __shfl_xor_sync(0xffffffffu, rs0, 2);
        rs1 += __shfl_xor_sync(0xffffffffu, rs1, 1);
        rs1 += __shfl_xor_sync(0xffffffffu, rs1, 2);
        l0 = l0 * al0 + rs0;
        l1 = l1 * al1 + rs1;

#pragma unroll
        for (int nt = 0; nt < 16; nt++) {
            o[nt][0] *= al0; o[nt][1] *= al0;
            o[nt][2] *= al1; o[nt][3] *= al1;
        }

        // ---- O += P @ V ----
#pragma unroll
        for (int ks = 0; ks < 8; ks++) {
            const int src1 = (g << 2) | (tg >> 1);
            uint32_t u0 = __shfl_sync(0xffffffffu, pf[ks][0], src1);
            uint32_t u1 = __shfl_sync(0xffffffffu, pf[ks][1], src1);
            uint32_t u2 = __shfl_sync(0xffffffffu, pf[ks][2], src1);
            uint32_t u3 = __shfl_sync(0xffffffffu, pf[ks][3], src1);
            uint32_t w0 = __shfl_sync(0xffffffffu, pf[ks][0], src1 + 2);
            uint32_t w1 = __shfl_sync(0xffffffffu, pf[ks][1], src1 + 2);
            uint32_t w2 = __shfl_sync(0xffffffffu, pf[ks][2], src1 + 2);
            uint32_t w3 = __shfl_sync(0xffffffffu, pf[ks][3], src1 + 2);
            uint32_t a[4];
            a[0] = (tg & 1) ? u1 : u0;
            a[1] = (tg & 1) ? u3 : u2;
            a[2] = (tg & 1) ? w1 : w0;
            a[3] = (tg & 1) ? w3 : w2;
#pragma unroll
            for (int nt = 0; nt < 16; nt++) {
                uint32_t bb[2];
                bb[0] = Vc[(ks*8+tg)*FVS   + nt*8 + g];
                bb[1] = Vc[(ks*8+tg+4)*FVS + nt*8 + g];
                mma_tf32(o[nt], a, bb);
            }
        }
        __syncthreads();
    }

    // ---- epilogue: normalize, tf32-round (feeds last GEMM), store ----
    const float inv0 = 1.0f / l0, inv1 = 1.0f / l1;
    float* og0 = g_O + (long)(b*T_ + t0 + wm + g) * (H_*HD_) + h*HD_;
    float* og1 = og0 + 8L * (H_*HD_);
#pragma unroll
    for (int nt = 0; nt < 16; nt++) {
        int c = nt*8 + 2*tg;
        *(float2*)(og0 + c) = make_float2(
            __uint_as_float(f2tf(o[nt][0]*inv0)),
            __uint_as_float(f2tf(o[nt][1]*inv0)));
        *(float2*)(og1 + c) = make_float2(
            __uint_as_float(f2tf(o[nt][2]*inv1)),
            __uint_as_float(f2tf(o[nt][3]*inv1)));
    }
}

// =====================================================================
// host launcher
// =====================================================================
extern "C" void kernel_launch(void* const* d_in, const int* in_sizes, int n_in,
                              void* d_out, int out_size)
{
    const float* x  = (const float*)d_in[0];
    const float* wq = (const float*)d_in[1];
    const float* bq = (const float*)d_in[2];
    const float* wk = (const float*)d_in[3];
    const float* bk = (const float*)d_in[4];
    const float* wv = (const float*)d_in[5];
    const float* bv = (const float*)d_in[6];
    const float* wo = (const float*)d_in[7];
    float* out = (float*)d_out;

    float *qp, *kp, *vp, *op;
    float *xr, *wqr, *wkr, *wvr, *wor;
    cudaGetSymbolAddress((void**)&qp, g_Q);
    cudaGetSymbolAddress((void**)&kp, g_K);
    cudaGetSymbolAddress((void**)&vp, g_V);
    cudaGetSymbolAddress((void**)&op, g_O);
    cudaGetSymbolAddress((void**)&xr,  g_Xr);
    cudaGetSymbolAddress((void**)&wqr, g_Wq);
    cudaGetSymbolAddress((void**)&wkr, g_Wk);
    cudaGetSymbolAddress((void**)&wvr, g_Wv);
    cudaGetSymbolAddress((void**)&wor, g_Wo);

    cudaFuncSetAttribute(flash_tc,
                         cudaFuncAttributeMaxDynamicSharedMemorySize, FLASH_SMEM);

    dim3 blk(256);

    // pre-round GEMM operands to tf32
    round_tf32_kernel<<<(MROWS*C_/4 + 255)/256,    blk>>>(x,  xr,  MROWS*C_/4);
    round_tf32_kernel<<<(C_*H_*HD_/4 + 255)/256,   blk>>>(wq, wqr, C_*H_*HD_/4);
    round_tf32_kernel<<<(C_*KVH_*HD_/4 + 255)/256, blk>>>(wk, wkr, C_*KVH_*HD_/4);
    round_tf32_kernel<<<(C_*KVH_*HD_/4 + 255)/256, blk>>>(wv, wvr, C_*KVH_*HD_/4);
    round_tf32_kernel<<<(H_*HD_*C_/4 + 255)/256,   blk>>>(wo, wor, H_*HD_*C_/4);

    // QKV projections (cp.async tf32 mma); V output rounded to tf32
    gemm_mma<<<dim3((H_*HD_)/128,   MROWS/128), blk>>>(xr, wqr, bq, qp, H_*HD_,   C_, 0);
    gemm_mma<<<dim3((KVH_*HD_)/128, MROWS/128), blk>>>(xr, wkr, bk, kp, KVH_*HD_, C_, 0);
    gemm_mma<<<dim3((KVH_*HD_)/128, MROWS/128), blk>>>(xr, wvr, bv, vp, KVH_*HD_, C_, 1);

    // RoPE (K output tf32-rounded)
    rope_q_kernel<<<(B_*T_*H_*64)/256, blk>>>();
    ropeT_k_kernel<<<dim3(T_/32, 2, B_*KVH_), blk>>>();

    // tensor-core flash attention
    flash_tc<<<dim3(T_/128, H_, B_), blk, FLASH_SMEM>>>();

    // output projection
    gemm_mma<<<dim3(C_/128, MROWS/128), blk>>>(op, wor, nullptr, out, C_, H_*HD_, 0);
}

// round 9
// speedup vs baseline: 1.9786x; 1.0687x over previous
#include <cuda_runtime.h>
#include <math.h>
#include <stdint.h>

#define B_   2
#define T_   2048
#define C_   2048
#define H_   16
#define KVH_ 4
#define HD_  128
#define MROWS (B_*T_)   // 4096

// ---------------- scratch (device globals; no allocations) ----------------
__device__ float g_Q[B_*T_*H_*HD_];
__device__ float g_K[B_*T_*KVH_*HD_];
__device__ float g_V[B_*T_*KVH_*HD_];     // tf32-rounded
__device__ float g_Kt[B_*KVH_*HD_*T_];    // tf32-rounded, [d][s] per (b,kh)
__device__ float g_O[B_*T_*H_*HD_];       // tf32-rounded
__device__ float g_Xr[B_*T_*C_];
__device__ float g_Wq[C_*H_*HD_];
__device__ float g_Wk[C_*KVH_*HD_];
__device__ float g_Wv[C_*KVH_*HD_];
__device__ float g_Wo[H_*HD_*C_];

// ==================== helpers ====================
__device__ __forceinline__ uint32_t smem_u32(const void* p) {
    uint32_t a;
    asm("{ .reg .u64 t; cvta.to.shared.u64 t, %1; cvt.u32.u64 %0, t; }"
        : "=r"(a) : "l"(p));
    return a;
}

__device__ __forceinline__ uint32_t f2tf(float f) {
    uint32_t r;
    asm("cvt.rna.tf32.f32 %0, %1;" : "=r"(r) : "f"(f));
    return r;
}

__device__ __forceinline__ void mma_tf32(float* c, const uint32_t* a, const uint32_t* b) {
    asm volatile(
        "mma.sync.aligned.m16n8k8.row.col.f32.tf32.tf32.f32 "
        "{%0,%1,%2,%3}, {%4,%5,%6,%7}, {%8,%9}, {%0,%1,%2,%3};"
        : "+f"(c[0]), "+f"(c[1]), "+f"(c[2]), "+f"(c[3])
        : "r"(a[0]), "r"(a[1]), "r"(a[2]), "r"(a[3]), "r"(b[0]), "r"(b[1]));
}

#define CPA16(dst, src) \
    asm volatile("cp.async.cg.shared.global [%0], [%1], 16;" \
                 :: "r"(dst), "l"(src) : "memory")
#define CP_COMMIT() asm volatile("cp.async.commit_group;" ::: "memory")
#define CP_WAIT1()  asm volatile("cp.async.wait_group 1;" ::: "memory")
#define CP_WAIT0()  asm volatile("cp.async.wait_group 0;" ::: "memory")

// =====================================================================
// Pre-round fp32 -> tf32-rounded fp32
// =====================================================================
__global__ void __launch_bounds__(256) round_tf32_kernel(
    const float* __restrict__ src, float* __restrict__ dst, int n4)
{
    int i = blockIdx.x * 256 + threadIdx.x;
    if (i < n4) {
        float4 v = *(const float4*)(src + (long)i * 4);
        v.x = __uint_as_float(f2tf(v.x));
        v.y = __uint_as_float(f2tf(v.y));
        v.z = __uint_as_float(f2tf(v.z));
        v.w = __uint_as_float(f2tf(v.w));
        *(float4*)(dst + (long)i * 4) = v;
    }
}

// =====================================================================
// GEMM core: C[128,128] tile = A[M,K] @ W[K,N] (+bias), tf32 mma.
// 3-stage cp.async pipeline, ONE __syncthreads per BK=16 iteration.
// A/W must be tf32-rounded fp32. 256 threads (8 warps 2x4), warp 64x32.
// dynamic smem = 3*(128*ASTRIDE + 16*BSTRIDE)*4 = 56064 B
// =====================================================================
#define ASTRIDE 20
#define BSTRIDE 132
#define GA_U32 (128*ASTRIDE)    // u32 per A stage
#define GB_U32 (16*BSTRIDE)     // u32 per B stage
#define GEMM_SMEM (3*(GA_U32+GB_U32)*4)

__device__ __forceinline__ void gemm_core(
    const float* __restrict__ A, const float* __restrict__ W,
    const float* __restrict__ bias, float* __restrict__ Cout,
    int N, int K, int rnd, int rowBlk, int colBlk)
{
    extern __shared__ uint32_t dsm[];
    uint32_t* Asm = dsm;                 // [3][GA_U32]
    uint32_t* Bsm = dsm + 3*GA_U32;      // [3][GB_U32]
    const uint32_t sbA = smem_u32(Asm);
    const uint32_t sbB = smem_u32(Bsm);

    const int tid  = threadIdx.x;
    const int wid  = tid >> 5;
    const int lane = tid & 31;
    const int g    = lane >> 2;
    const int tg   = lane & 3;
    const int warp_m = (wid & 1) * 64;
    const int warp_n = (wid >> 1) * 32;

    float acc[4][4][4];
#pragma unroll
    for (int mt = 0; mt < 4; mt++)
#pragma unroll
        for (int nt = 0; nt < 4; nt++)
#pragma unroll
            for (int i = 0; i < 4; i++) acc[mt][nt][i] = 0.f;

    const int nit = K / 16;

    // prefetch tile t into stage s
    auto prefetch = [&](int t, int s) {
#pragma unroll
        for (int i = 0; i < 2; i++) {
            int idx = tid + i * 256;
            int r = idx >> 2, c4 = (idx & 3) * 4;
            CPA16(sbA + (uint32_t)(s*GA_U32 + r*ASTRIDE + c4) * 4u,
                  (const void*)(A + (long)(rowBlk + r) * K + t*16 + c4));
        }
#pragma unroll
        for (int i = 0; i < 2; i++) {
            int idx = tid + i * 256;
            int k = idx >> 5, n4 = (idx & 31) * 4;
            CPA16(sbB + (uint32_t)(s*GB_U32 + k*BSTRIDE + n4) * 4u,
                  (const void*)(W + (long)(t*16 + k) * N + colBlk + n4));
        }
        CP_COMMIT();
    };

    prefetch(0, 0);
    prefetch(1, 1);

    for (int it = 0; it < nit; it++) {
        const int cur = it % 3;
        if (it == nit - 1) { CP_WAIT0(); } else { CP_WAIT1(); }
        __syncthreads();
        if (it + 2 < nit) prefetch(it + 2, (it + 2) % 3);

        const uint32_t* As = Asm + cur * GA_U32;
        const uint32_t* Bs = Bsm + cur * GB_U32;
#pragma unroll
        for (int ks = 0; ks < 16; ks += 8) {
            uint32_t afr[4][4], bfr[4][2];
#pragma unroll
            for (int mt = 0; mt < 4; mt++) {
                int arow = warp_m + mt * 16 + g;
                int acol = ks + tg;
                afr[mt][0] = As[arow * ASTRIDE + acol];
                afr[mt][1] = As[(arow + 8) * ASTRIDE + acol];
                afr[mt][2] = As[arow * ASTRIDE + acol + 4];
                afr[mt][3] = As[(arow + 8) * ASTRIDE + acol + 4];
            }
#pragma unroll
            for (int nt = 0; nt < 4; nt++) {
                int brow = ks + tg;
                int bcol = warp_n + nt * 8 + g;
                bfr[nt][0] = Bs[brow * BSTRIDE + bcol];
                bfr[nt][1] = Bs[(brow + 4) * BSTRIDE + bcol];
            }
#pragma unroll
            for (int mt = 0; mt < 4; mt++)
#pragma unroll
                for (int nt = 0; nt < 4; nt++)
                    mma_tf32(acc[mt][nt], afr[mt], bfr[nt]);
        }
    }

#pragma unroll
    for (int mt = 0; mt < 4; mt++) {
        int row = rowBlk + warp_m + mt * 16 + g;
#pragma unroll
        for (int nt = 0; nt < 4; nt++) {
            int col = colBlk + warp_n + nt * 8 + 2 * tg;
            float b0 = 0.f, b1 = 0.f;
            if (bias) { b0 = bias[col]; b1 = bias[col + 1]; }
            float v0 = acc[mt][nt][0] + b0, v1 = acc[mt][nt][1] + b1;
            float v2 = acc[mt][nt][2] + b0, v3 = acc[mt][nt][3] + b1;
            if (rnd) {
                v0 = __uint_as_float(f2tf(v0)); v1 = __uint_as_float(f2tf(v1));
                v2 = __uint_as_float(f2tf(v2)); v3 = __uint_as_float(f2tf(v3));
            }
            float* c0 = Cout + (long)row * N + col;
            float* c1 = Cout + (long)(row + 8) * N + col;
            *(float2*)c0 = make_float2(v0, v1);
            *(float2*)c1 = make_float2(v2, v3);
        }
    }
}

// Merged QKV projection: grid (24, 32). bx<16: Q, <20: K, else V.
__global__ void __launch_bounds__(256) qkv_mma(
    const float* __restrict__ xr,
    const float* __restrict__ wq, const float* __restrict__ bq, float* __restrict__ qp,
    const float* __restrict__ wk, const float* __restrict__ bk, float* __restrict__ kp,
    const float* __restrict__ wv, const float* __restrict__ bv, float* __restrict__ vp)
{
    const int bx = blockIdx.x;
    const int rowBlk = blockIdx.y * 128;
    if (bx < 16)
        gemm_core(xr, wq, bq, qp, H_*HD_,   C_, 0, rowBlk, bx * 128);
    else if (bx < 20)
        gemm_core(xr, wk, bk, kp, KVH_*HD_, C_, 0, rowBlk, (bx - 16) * 128);
    else
        gemm_core(xr, wv, bv, vp, KVH_*HD_, C_, 1, rowBlk, (bx - 20) * 128);
}

// Generic single GEMM (output projection)
__global__ void __launch_bounds__(256) gemm_mma(
    const float* __restrict__ A, const float* __restrict__ W,
    const float* __restrict__ bias, float* __restrict__ Cout,
    int N, int K, int rnd)
{
    gemm_core(A, W, bias, Cout, N, K, rnd, blockIdx.y * 128, blockIdx.x * 128);
}

// =====================================================================
// RoPE on Q, in place.
// =====================================================================
__global__ void __launch_bounds__(256) rope_q_kernel()
{
    int idx = blockIdx.x * 256 + threadIdx.x;
    int d  = idx & 63;
    int rh = idx >> 6;
    int h  = rh & (H_ - 1);
    int bt = rh >> 4;
    int t  = bt & (T_ - 1);
    long base = (long)bt * (H_*HD_) + h * HD_;
    float invf = expf(-(float)d * (9.210340371976184f / 64.0f));
    float sn, cs;
    sincosf((float)t * invf, &sn, &cs);
    float x1 = g_Q[base + d];
    float x2 = g_Q[base + d + 64];
    g_Q[base + d]      = x1 * cs - x2 * sn;
    g_Q[base + d + 64] = x2 * cs + x1 * sn;
}

// =====================================================================
// RoPE on K + transpose to [B,KVH,HD,T]; output tf32-ROUNDED.
// =====================================================================
__global__ void __launch_bounds__(256) ropeT_k_kernel()
{
    __shared__ float sm1[32][33];
    __shared__ float sm2[32][33];
    const int tid = threadIdx.x;
    const int s0  = blockIdx.x * 32;
    const int d0  = blockIdx.y * 32;
    const int bkh = blockIdx.z;
    const int b   = bkh >> 2;
    const int kh  = bkh & 3;

    {
        int r  = tid >> 3;
        int c4 = (tid & 7) * 4;
        long gbase = (long)(b*T_ + s0 + r) * (KVH_*HD_) + kh * HD_;
        float4 v1 = *(const float4*)(g_K + gbase + d0 + c4);
        float4 v2 = *(const float4*)(g_K + gbase + d0 + 64 + c4);
        sm1[r][c4+0]=v1.x; sm1[r][c4+1]=v1.y; sm1[r][c4+2]=v1.z; sm1[r][c4+3]=v1.w;
        sm2[r][c4+0]=v2.x; sm2[r][c4+1]=v2.y; sm2[r][c4+2]=v2.z; sm2[r][c4+3]=v2.w;
    }
    __syncthreads();

    const int dl = tid >> 2;
    const int cg = tid & 3;
    const int dd = dl & 31;
    float invf = expf(-(float)(d0 + dd) * (9.210340371976184f / 64.0f));
    int dglob = (dl < 32) ? (d0 + dd) : (64 + d0 + dd);
    long obase = (long)(bkh * HD_ + dglob) * T_;
#pragma unroll
    for (int i = 0; i < 8; i++) {
        int cc = cg * 8 + i;
        int t  = s0 + cc;
        float sn, cs;
        sincosf((float)t * invf, &sn, &cs);
        float x1 = sm1[cc][dd];
        float x2 = sm2[cc][dd];
        float out = (dl < 32) ? (x1 * cs - x2 * sn) : (x2 * cs + x1 * sn);
        g_Kt[obase + t] = __uint_as_float(f2tf(out));
    }
}

// =====================================================================
// Tensor-core flash attention (causal, GQA).  (R6/R8 proven structure)
// =====================================================================
#define FQS 132
#define FKS 68
#define FVS 132
#define KOFF 67584
#define KSZ  34816
#define VOFF (KOFF + 2*KSZ)
#define VSZ  33792
#define FLASH_SMEM (VOFF + 2*VSZ)  // 204800

__global__ void __launch_bounds__(256) flash_tc()
{
    extern __shared__ char smem[];
    uint32_t* Qs  = (uint32_t*)smem;
    const uint32_t sb = smem_u32(smem);

    const int tid = threadIdx.x;
    const int qt  = blockIdx.x;
    const int h   = blockIdx.y;
    const int b   = blockIdx.z;
    const int kh  = h >> 2;
    const int t0  = qt * 128;
    const int wm  = (tid >> 5) * 16;
    const int lane = tid & 31;
    const int g = lane >> 2, tg = lane & 3;

    const float* kg = g_Kt + (long)(b*KVH_ + kh) * HD_ * T_;
    const float* vg = g_V  + (long)b*T_*(KVH_*HD_) + kh*HD_;
    const float scale = 0.08838834764831845f;

    {
        const float* qg = g_Q + (long)(b*T_ + t0) * (H_*HD_) + h*HD_;
#pragma unroll
        for (int it = 0; it < 16; it++) {
            int idx = tid + it*256;
            int r = idx >> 5, d4 = (idx & 31) * 4;
            float4 v = *(const float4*)(qg + (long)r*(H_*HD_) + d4);
            uint32_t* qp = &Qs[r*FQS + d4];
            qp[0] = f2tf(v.x * scale); qp[1] = f2tf(v.y * scale);
            qp[2] = f2tf(v.z * scale); qp[3] = f2tf(v.w * scale);
        }
    }

    const int nkt = 2*qt + 2;

    {
        const int s0n = 0;
#pragma unroll
        for (int it = 0; it < 8; it++) {
            int idx = tid + it*256;
            int d = idx >> 4, c4 = (idx & 15) * 4;
            CPA16(sb + KOFF + (d*FKS + c4)*4, (const void*)(kg + (long)d*T_ + s0n + c4));
        }
#pragma unroll
        for (int it = 0; it < 8; it++) {
            int idx = tid + it*256;
            int c = idx >> 5, d4 = (idx & 31) * 4;
            CPA16(sb + VOFF + (c*FVS + d4)*4, (const void*)(vg + (long)(s0n + c)*(KVH_*HD_) + d4));
        }
        CP_COMMIT();
    }

    float o[16][4];
#pragma unroll
    for (int nt = 0; nt < 16; nt++)
#pragma unroll
        for (int i = 0; i < 4; i++) o[nt][i] = 0.f;
    float m0 = -1e30f, m1 = -1e30f, l0 = 0.f, l1 = 0.f;

    for (int kt = 0; kt < nkt; kt++) {
        const int cur = kt & 1;
        if (kt + 1 < nkt) {
            const int s0n = (kt + 1) * 64;
            const int sel = cur ^ 1;
#pragma unroll
            for (int it = 0; it < 8; it++) {
                int idx = tid + it*256;
                int d = idx >> 4, c4 = (idx & 15) * 4;
                CPA16(sb + KOFF + sel*KSZ + (d*FKS + c4)*4,
                      (const void*)(kg + (long)d*T_ + s0n + c4));
            }
#pragma unroll
            for (int it = 0; it < 8; it++) {
                int idx = tid + it*256;
                int c = idx >> 5, d4 = (idx & 31) * 4;
                CPA16(sb + VOFF + sel*VSZ + (c*FVS + d4)*4,
                      (const void*)(vg + (long)(s0n + c)*(KVH_*HD_) + d4));
            }
            CP_COMMIT();
            CP_WAIT1();
        } else {
            CP_WAIT0();
        }
        __syncthreads();

        const uint32_t* Kc = (const uint32_t*)(smem + KOFF + cur*KSZ);
        const uint32_t* Vc = (const uint32_t*)(smem + VOFF + cur*VSZ);

        float sf[8][4];
#pragma unroll
        for (int nt = 0; nt < 8; nt++)
#pragma unroll
            for (int i = 0; i < 4; i++) sf[nt][i] = 0.f;

#pragma unroll
        for (int kd = 0; kd < 16; kd++) {
            uint32_t a[4];
            a[0] = Qs[(wm+g)*FQS   + kd*8 + tg];
            a[1] = Qs[(wm+g+8)*FQS + kd*8 + tg];
            a[2] = Qs[(wm+g)*FQS   + kd*8 + tg + 4];
            a[3] = Qs[(wm+g+8)*FQS + kd*8 + tg + 4];
#pragma unroll
            for (int nt = 0; nt < 8; nt++) {
                uint32_t bb[2];
                bb[0] = Kc[(kd*8+tg)*FKS   + nt*8 + g];
                bb[1] = Kc[(kd*8+tg+4)*FKS + nt*8 + g];
                mma_tf32(sf[nt], a, bb);
            }
        }

        if (kt >= nkt - 2) {
            const int s0c = kt * 64;
            const int r0 = t0 + wm + g, r1 = r0 + 8;
#pragma unroll
            for (int nt = 0; nt < 8; nt++) {
                int c0 = s0c + nt*8 + 2*tg;
                if (c0     > r0) sf[nt][0] = -1e30f;
                if (c0 + 1 > r0) sf[nt][1] = -1e30f;
                if (c0     > r1) sf[nt][2] = -1e30f;
                if (c0 + 1 > r1) sf[nt][3] = -1e30f;
            }
        }

        float mt0 = -1e30f, mt1 = -1e30f;
#pragma unroll
        for (int nt = 0; nt < 8; nt++) {
            mt0 = fmaxf(mt0, fmaxf(sf[nt][0], sf[nt][1]));
            mt1 = fmaxf(mt1, fmaxf(sf[nt][2], sf[nt][3]));
        }
        mt0 = fmaxf(mt0, __shfl_xor_sync(0xffffffffu, mt0, 1));
        mt0 = fmaxf(mt0, __shfl_xor_sync(0xffffffffu, mt0, 2));
        mt1 = fmaxf(mt1, __shfl_xor_sync(0xffffffffu, mt1, 1));
        mt1 = fmaxf(mt1, __shfl_xor_sync(0xffffffffu, mt1, 2));

        float mn0 = fmaxf(m0, mt0), mn1 = fmaxf(m1, mt1);
        float al0 = __expf(m0 - mn0), al1 = __expf(m1 - mn1);
        m0 = mn0; m1 = mn1;

        float rs0 = 0.f, rs1 = 0.f;
        uint32_t pf[8][4];
#pragma unroll
        for (int nt = 0; nt < 8; nt++) {
            float p0 = __expf(sf[nt][0] - mn0);
            float p1 = __expf(sf[nt][1] - mn0);
            float p2 = __expf(sf[nt][2] - mn1);
            float p3 = __expf(sf[nt][3] - mn1);
            rs0 += p0 + p1; rs1 += p2 + p3;
            pf[nt][0] = f2tf(p0); pf[nt][1] = f2tf(p1);
            pf[nt][2] = f2tf(p2); pf[nt][3] = f2tf(p3);
        }
        rs0 += __shfl_xor_sync(0xffffffffu, rs0, 1);
        rs0 += __shfl_xor_sync(0xffffffffu, rs0, 2);
        rs1 += __shfl_xor_sync(0xffffffffu, rs1, 1);
        rs1 += __shfl_xor_sync(0xffffffffu, rs1, 2);
        l0 = l0 * al0 + rs0;
        l1 = l1 * al1 + rs1;

#pragma unroll
        for (int nt = 0; nt < 16; nt++) {
            o[nt][0] *= al0; o[nt][1] *= al0;
            o[nt][2] *= al1; o[nt][3] *= al1;
        }

#pragma unroll
        for (int ks = 0; ks < 8; ks++) {
            const int src1 = (g << 2) | (tg >> 1);
            uint32_t u0 = __shfl_sync(0xffffffffu, pf[ks][0], src1);
            uint32_t u1 = __shfl_sync(0xffffffffu, pf[ks][1], src1);
            uint32_t u2 = __shfl_sync(0xffffffffu, pf[ks][2], src1);
            uint32_t u3 = __shfl_sync(0xffffffffu, pf[ks][3], src1);
            uint32_t w0 = __shfl_sync(0xffffffffu, pf[ks][0], src1 + 2);
            uint32_t w1 = __shfl_sync(0xffffffffu, pf[ks][1], src1 + 2);
            uint32_t w2 = __shfl_sync(0xffffffffu, pf[ks][2], src1 + 2);
            uint32_t w3 = __shfl_sync(0xffffffffu, pf[ks][3], src1 + 2);
            uint32_t a[4];
            a[0] = (tg & 1) ? u1 : u0;
            a[1] = (tg & 1) ? u3 : u2;
            a[2] = (tg & 1) ? w1 : w0;
            a[3] = (tg & 1) ? w3 : w2;
#pragma unroll
            for (int nt = 0; nt < 16; nt++) {
                uint32_t bb[2];
                bb[0] = Vc[(ks*8+tg)*FVS   + nt*8 + g];
                bb[1] = Vc[(ks*8+tg+4)*FVS + nt*8 + g];
                mma_tf32(o[nt], a, bb);
            }
        }
        __syncthreads();
    }

    const float inv0 = 1.0f / l0, inv1 = 1.0f / l1;
    float* og0 = g_O + (long)(b*T_ + t0 + wm + g) * (H_*HD_) + h*HD_;
    float* og1 = og0 + 8L * (H_*HD_);
#pragma unroll
    for (int nt = 0; nt < 16; nt++) {
        int c = nt*8 + 2*tg;
        *(float2*)(og0 + c) = make_float2(
            __uint_as_float(f2tf(o[nt][0]*inv0)),
            __uint_as_float(f2tf(o[nt][1]*inv0)));
        *(float2*)(og1 + c) = make_float2(
            __uint_as_float(f2tf(o[nt][2]*inv1)),
            __uint_as_float(f2tf(o[nt][3]*inv1)));
    }
}

// =====================================================================
// host launcher
// =====================================================================
extern "C" void kernel_launch(void* const* d_in, const int* in_sizes, int n_in,
                              void* d_out, int out_size)
{
    const float* x  = (const float*)d_in[0];
    const float* wq = (const float*)d_in[1];
    const float* bq = (const float*)d_in[2];
    const float* wk = (const float*)d_in[3];
    const float* bk = (const float*)d_in[4];
    const float* wv = (const float*)d_in[5];
    const float* bv = (const float*)d_in[6];
    const float* wo = (const float*)d_in[7];
    float* out = (float*)d_out;

    float *qp, *kp, *vp, *op;
    float *xr, *wqr, *wkr, *wvr, *wor;
    cudaGetSymbolAddress((void**)&qp, g_Q);
    cudaGetSymbolAddress((void**)&kp, g_K);
    cudaGetSymbolAddress((void**)&vp, g_V);
    cudaGetSymbolAddress((void**)&op, g_O);
    cudaGetSymbolAddress((void**)&xr,  g_Xr);
    cudaGetSymbolAddress((void**)&wqr, g_Wq);
    cudaGetSymbolAddress((void**)&wkr, g_Wk);
    cudaGetSymbolAddress((void**)&wvr, g_Wv);
    cudaGetSymbolAddress((void**)&wor, g_Wo);

    cudaFuncSetAttribute(flash_tc,
                         cudaFuncAttributeMaxDynamicSharedMemorySize, FLASH_SMEM);
    cudaFuncSetAttribute(qkv_mma,
                         cudaFuncAttributeMaxDynamicSharedMemorySize, GEMM_SMEM);
    cudaFuncSetAttribute(gemm_mma,
                         cudaFuncAttributeMaxDynamicSharedMemorySize, GEMM_SMEM);

    dim3 blk(256);

    // pre-round GEMM operands to tf32
    round_tf32_kernel<<<(MROWS*C_/4 + 255)/256,    blk>>>(x,  xr,  MROWS*C_/4);
    round_tf32_kernel<<<(C_*H_*HD_/4 + 255)/256,   blk>>>(wq, wqr, C_*H_*HD_/4);
    round_tf32_kernel<<<(C_*KVH_*HD_/4 + 255)/256, blk>>>(wk, wkr, C_*KVH_*HD_/4);
    round_tf32_kernel<<<(C_*KVH_*HD_/4 + 255)/256, blk>>>(wv, wvr, C_*KVH_*HD_/4);
    round_tf32_kernel<<<(H_*HD_*C_/4 + 255)/256,   blk>>>(wo, wor, H_*HD_*C_/4);

    // merged QKV projection (one launch, 768 CTAs)
    qkv_mma<<<dim3(24, MROWS/128), blk, GEMM_SMEM>>>(
        xr, wqr, bq, qp, wkr, bk, kp, wvr, bv, vp);

    // RoPE
    rope_q_kernel<<<(B_*T_*H_*64)/256, blk>>>();
    ropeT_k_kernel<<<dim3(T_/32, 2, B_*KVH_), blk>>>();

    // tensor-core flash attention
    flash_tc<<<dim3(T_/128, H_, B_), blk, FLASH_SMEM>>>();

    // output projection
    gemm_mma<<<dim3(C_/128, MROWS/128), blk, GEMM_SMEM>>>(op, wor, nullptr, out, C_, H_*HD_, 0);
}

// round 10
// speedup vs baseline: 2.0156x; 1.0187x over previous
#include <cuda_runtime.h>
#include <math.h>
#include <stdint.h>

#define B_   2
#define T_   2048
#define C_   2048
#define H_   16
#define KVH_ 4
#define HD_  128
#define MROWS (B_*T_)   // 4096

// ---------------- scratch (device globals; no allocations) ----------------
__device__ float g_Q[B_*T_*H_*HD_];
__device__ float g_K[B_*T_*KVH_*HD_];
__device__ float g_V[B_*T_*KVH_*HD_];     // tf32-rounded
__device__ float g_Kt[B_*KVH_*HD_*T_];    // tf32-rounded, [d][s] per (b,kh)
__device__ float g_O[B_*T_*H_*HD_];       // tf32-rounded
__device__ float g_Xr[B_*T_*C_];
__device__ float g_Wq[C_*H_*HD_];
__device__ float g_Wk[C_*KVH_*HD_];
__device__ float g_Wv[C_*KVH_*HD_];
__device__ float g_Wo[H_*HD_*C_];

// ==================== helpers ====================
__device__ __forceinline__ uint32_t smem_u32(const void* p) {
    uint32_t a;
    asm("{ .reg .u64 t; cvta.to.shared.u64 t, %1; cvt.u32.u64 %0, t; }"
        : "=r"(a) : "l"(p));
    return a;
}

__device__ __forceinline__ uint32_t f2tf(float f) {
    uint32_t r;
    asm("cvt.rna.tf32.f32 %0, %1;" : "=r"(r) : "f"(f));
    return r;
}

__device__ __forceinline__ void mma_tf32(float* c, const uint32_t* a, const uint32_t* b) {
    asm volatile(
        "mma.sync.aligned.m16n8k8.row.col.f32.tf32.tf32.f32 "
        "{%0,%1,%2,%3}, {%4,%5,%6,%7}, {%8,%9}, {%0,%1,%2,%3};"
        : "+f"(c[0]), "+f"(c[1]), "+f"(c[2]), "+f"(c[3])
        : "r"(a[0]), "r"(a[1]), "r"(a[2]), "r"(a[3]), "r"(b[0]), "r"(b[1]));
}

#define CPA16(dst, src) \
    asm volatile("cp.async.cg.shared.global [%0], [%1], 16;" \
                 :: "r"(dst), "l"(src) : "memory")
#define CP_COMMIT() asm volatile("cp.async.commit_group;" ::: "memory")
#define CP_WAIT1()  asm volatile("cp.async.wait_group 1;" ::: "memory")
#define CP_WAIT0()  asm volatile("cp.async.wait_group 0;" ::: "memory")

// =====================================================================
// Pre-round fp32 -> tf32-rounded fp32
// =====================================================================
__global__ void __launch_bounds__(256) round_tf32_kernel(
    const float* __restrict__ src, float* __restrict__ dst, int n4)
{
    int i = blockIdx.x * 256 + threadIdx.x;
    if (i < n4) {
        float4 v = *(const float4*)(src + (long)i * 4);
        v.x = __uint_as_float(f2tf(v.x));
        v.y = __uint_as_float(f2tf(v.y));
        v.z = __uint_as_float(f2tf(v.z));
        v.w = __uint_as_float(f2tf(v.w));
        *(float4*)(dst + (long)i * 4) = v;
    }
}

// =====================================================================
// GEMM core: CTA tile 256x128, 8 warps (4m x 2n), warp tile 64x64.
// tf32 mma, 3-stage cp.async pipeline, one __syncthreads per BK=16.
// LDS:MMA ratio 1.0 (16 A + 16 B loads per 32 MMAs per 8-slice).
// dynamic smem = 3*(256*ASTRIDE + 16*BSTRIDE)*4 = 86784 B
// =====================================================================
#define ASTRIDE 20
#define BSTRIDE 132
#define GA_U32 (256*ASTRIDE)    // u32 per A stage
#define GB_U32 (16*BSTRIDE)     // u32 per B stage
#define GEMM_SMEM (3*(GA_U32+GB_U32)*4)

__device__ __forceinline__ void gemm_core(
    const float* __restrict__ A, const float* __restrict__ W,
    const float* __restrict__ bias, float* __restrict__ Cout,
    int N, int K, int rnd, int rowBlk, int colBlk)
{
    extern __shared__ uint32_t dsm[];
    uint32_t* Asm = dsm;                 // [3][GA_U32]
    uint32_t* Bsm = dsm + 3*GA_U32;      // [3][GB_U32]
    const uint32_t sbA = smem_u32(Asm);
    const uint32_t sbB = smem_u32(Bsm);

    const int tid  = threadIdx.x;
    const int wid  = tid >> 5;
    const int lane = tid & 31;
    const int g    = lane >> 2;
    const int tg   = lane & 3;
    const int warp_m = (wid & 3) * 64;    // 4 warps over 256 rows
    const int warp_n = (wid >> 2) * 64;   // 2 warps over 128 cols

    float acc[4][8][4];
#pragma unroll
    for (int mt = 0; mt < 4; mt++)
#pragma unroll
        for (int nt = 0; nt < 8; nt++)
#pragma unroll
            for (int i = 0; i < 4; i++) acc[mt][nt][i] = 0.f;

    const int nit = K / 16;

    // prefetch tile t into stage s
    auto prefetch = [&](int t, int s) {
#pragma unroll
        for (int i = 0; i < 4; i++) {
            int idx = tid + i * 256;
            int r = idx >> 2, c4 = (idx & 3) * 4;
            CPA16(sbA + (uint32_t)(s*GA_U32 + r*ASTRIDE + c4) * 4u,
                  (const void*)(A + (long)(rowBlk + r) * K + t*16 + c4));
        }
#pragma unroll
        for (int i = 0; i < 2; i++) {
            int idx = tid + i * 256;
            int k = idx >> 5, n4 = (idx & 31) * 4;
            CPA16(sbB + (uint32_t)(s*GB_U32 + k*BSTRIDE + n4) * 4u,
                  (const void*)(W + (long)(t*16 + k) * N + colBlk + n4));
        }
        CP_COMMIT();
    };

    prefetch(0, 0);
    prefetch(1, 1);

    for (int it = 0; it < nit; it++) {
        const int cur = it % 3;
        if (it == nit - 1) { CP_WAIT0(); } else { CP_WAIT1(); }
        __syncthreads();
        if (it + 2 < nit) prefetch(it + 2, (it + 2) % 3);

        const uint32_t* As = Asm + cur * GA_U32;
        const uint32_t* Bs = Bsm + cur * GB_U32;
#pragma unroll
        for (int ks = 0; ks < 16; ks += 8) {
            uint32_t afr[4][4], bfr[8][2];
#pragma unroll
            for (int mt = 0; mt < 4; mt++) {
                int arow = warp_m + mt * 16 + g;
                int acol = ks + tg;
                afr[mt][0] = As[arow * ASTRIDE + acol];
                afr[mt][1] = As[(arow + 8) * ASTRIDE + acol];
                afr[mt][2] = As[arow * ASTRIDE + acol + 4];
                afr[mt][3] = As[(arow + 8) * ASTRIDE + acol + 4];
            }
#pragma unroll
            for (int nt = 0; nt < 8; nt++) {
                int brow = ks + tg;
                int bcol = warp_n + nt * 8 + g;
                bfr[nt][0] = Bs[brow * BSTRIDE + bcol];
                bfr[nt][1] = Bs[(brow + 4) * BSTRIDE + bcol];
            }
#pragma unroll
            for (int mt = 0; mt < 4; mt++)
#pragma unroll
                for (int nt = 0; nt < 8; nt++)
                    mma_tf32(acc[mt][nt], afr[mt], bfr[nt]);
        }
    }

#pragma unroll
    for (int mt = 0; mt < 4; mt++) {
        int row = rowBlk + warp_m + mt * 16 + g;
#pragma unroll
        for (int nt = 0; nt < 8; nt++) {
            int col = colBlk + warp_n + nt * 8 + 2 * tg;
            float b0 = 0.f, b1 = 0.f;
            if (bias) { b0 = bias[col]; b1 = bias[col + 1]; }
            float v0 = acc[mt][nt][0] + b0, v1 = acc[mt][nt][1] + b1;
            float v2 = acc[mt][nt][2] + b0, v3 = acc[mt][nt][3] + b1;
            if (rnd) {
                v0 = __uint_as_float(f2tf(v0)); v1 = __uint_as_float(f2tf(v1));
                v2 = __uint_as_float(f2tf(v2)); v3 = __uint_as_float(f2tf(v3));
            }
            float* c0 = Cout + (long)row * N + col;
            float* c1 = Cout + (long)(row + 8) * N + col;
            *(float2*)c0 = make_float2(v0, v1);
            *(float2*)c1 = make_float2(v2, v3);
        }
    }
}

// Merged QKV projection: grid (24, 16). bx<16: Q, <20: K, else V.
__global__ void __launch_bounds__(256) qkv_mma(
    const float* __restrict__ xr,
    const float* __restrict__ wq, const float* __restrict__ bq, float* __restrict__ qp,
    const float* __restrict__ wk, const float* __restrict__ bk, float* __restrict__ kp,
    const float* __restrict__ wv, const float* __restrict__ bv, float* __restrict__ vp)
{
    const int bx = blockIdx.x;
    const int rowBlk = blockIdx.y * 256;
    if (bx < 16)
        gemm_core(xr, wq, bq, qp, H_*HD_,   C_, 0, rowBlk, bx * 128);
    else if (bx < 20)
        gemm_core(xr, wk, bk, kp, KVH_*HD_, C_, 0, rowBlk, (bx - 16) * 128);
    else
        gemm_core(xr, wv, bv, vp, KVH_*HD_, C_, 1, rowBlk, (bx - 20) * 128);
}

// Generic single GEMM (output projection): grid (N/128, M/256)
__global__ void __launch_bounds__(256) gemm_mma(
    const float* __restrict__ A, const float* __restrict__ W,
    const float* __restrict__ bias, float* __restrict__ Cout,
    int N, int K, int rnd)
{
    gemm_core(A, W, bias, Cout, N, K, rnd, blockIdx.y * 256, blockIdx.x * 128);
}

// =====================================================================
// RoPE on Q, in place.
// =====================================================================
__global__ void __launch_bounds__(256) rope_q_kernel()
{
    int idx = blockIdx.x * 256 + threadIdx.x;
    int d  = idx & 63;
    int rh = idx >> 6;
    int h  = rh & (H_ - 1);
    int bt = rh >> 4;
    int t  = bt & (T_ - 1);
    long base = (long)bt * (H_*HD_) + h * HD_;
    float invf = expf(-(float)d * (9.210340371976184f / 64.0f));
    float sn, cs;
    sincosf((float)t * invf, &sn, &cs);
    float x1 = g_Q[base + d];
    float x2 = g_Q[base + d + 64];
    g_Q[base + d]      = x1 * cs - x2 * sn;
    g_Q[base + d + 64] = x2 * cs + x1 * sn;
}

// =====================================================================
// RoPE on K + transpose to [B,KVH,HD,T]; output tf32-ROUNDED.
// =====================================================================
__global__ void __launch_bounds__(256) ropeT_k_kernel()
{
    __shared__ float sm1[32][33];
    __shared__ float sm2[32][33];
    const int tid = threadIdx.x;
    const int s0  = blockIdx.x * 32;
    const int d0  = blockIdx.y * 32;
    const int bkh = blockIdx.z;
    const int b   = bkh >> 2;
    const int kh  = bkh & 3;

    {
        int r  = tid >> 3;
        int c4 = (tid & 7) * 4;
        long gbase = (long)(b*T_ + s0 + r) * (KVH_*HD_) + kh * HD_;
        float4 v1 = *(const float4*)(g_K + gbase + d0 + c4);
        float4 v2 = *(const float4*)(g_K + gbase + d0 + 64 + c4);
        sm1[r][c4+0]=v1.x; sm1[r][c4+1]=v1.y; sm1[r][c4+2]=v1.z; sm1[r][c4+3]=v1.w;
        sm2[r][c4+0]=v2.x; sm2[r][c4+1]=v2.y; sm2[r][c4+2]=v2.z; sm2[r][c4+3]=v2.w;
    }
    __syncthreads();

    const int dl = tid >> 2;
    const int cg = tid & 3;
    const int dd = dl & 31;
    float invf = expf(-(float)(d0 + dd) * (9.210340371976184f / 64.0f));
    int dglob = (dl < 32) ? (d0 + dd) : (64 + d0 + dd);
    long obase = (long)(bkh * HD_ + dglob) * T_;
#pragma unroll
    for (int i = 0; i < 8; i++) {
        int cc = cg * 8 + i;
        int t  = s0 + cc;
        float sn, cs;
        sincosf((float)t * invf, &sn, &cs);
        float x1 = sm1[cc][dd];
        float x2 = sm2[cc][dd];
        float out = (dl < 32) ? (x1 * cs - x2 * sn) : (x2 * cs + x1 * sn);
        g_Kt[obase + t] = __uint_as_float(f2tf(out));
    }
}

// =====================================================================
// Tensor-core flash attention (causal, GQA).  (proven structure)
// =====================================================================
#define FQS 132
#define FKS 68
#define FVS 132
#define KOFF 67584
#define KSZ  34816
#define VOFF (KOFF + 2*KSZ)
#define VSZ  33792
#define FLASH_SMEM (VOFF + 2*VSZ)  // 204800

__global__ void __launch_bounds__(256) flash_tc()
{
    extern __shared__ char smem[];
    uint32_t* Qs  = (uint32_t*)smem;
    const uint32_t sb = smem_u32(smem);

    const int tid = threadIdx.x;
    const int qt  = blockIdx.x;
    const int h   = blockIdx.y;
    const int b   = blockIdx.z;
    const int kh  = h >> 2;
    const int t0  = qt * 128;
    const int wm  = (tid >> 5) * 16;
    const int lane = tid & 31;
    const int g = lane >> 2, tg = lane & 3;

    const float* kg = g_Kt + (long)(b*KVH_ + kh) * HD_ * T_;
    const float* vg = g_V  + (long)b*T_*(KVH_*HD_) + kh*HD_;
    const float scale = 0.08838834764831845f;

    {
        const float* qg = g_Q + (long)(b*T_ + t0) * (H_*HD_) + h*HD_;
#pragma unroll
        for (int it = 0; it < 16; it++) {
            int idx = tid + it*256;
            int r = idx >> 5, d4 = (idx & 31) * 4;
            float4 v = *(const float4*)(qg + (long)r*(H_*HD_) + d4);
            uint32_t* qp = &Qs[r*FQS + d4];
            qp[0] = f2tf(v.x * scale); qp[1] = f2tf(v.y * scale);
            qp[2] = f2tf(v.z * scale); qp[3] = f2tf(v.w * scale);
        }
    }

    const int nkt = 2*qt + 2;

    {
        const int s0n = 0;
#pragma unroll
        for (int it = 0; it < 8; it++) {
            int idx = tid + it*256;
            int d = idx >> 4, c4 = (idx & 15) * 4;
            CPA16(sb + KOFF + (d*FKS + c4)*4, (const void*)(kg + (long)d*T_ + s0n + c4));
        }
#pragma unroll
        for (int it = 0; it < 8; it++) {
            int idx = tid + it*256;
            int c = idx >> 5, d4 = (idx & 31) * 4;
            CPA16(sb + VOFF + (c*FVS + d4)*4, (const void*)(vg + (long)(s0n + c)*(KVH_*HD_) + d4));
        }
        CP_COMMIT();
    }

    float o[16][4];
#pragma unroll
    for (int nt = 0; nt < 16; nt++)
#pragma unroll
        for (int i = 0; i < 4; i++) o[nt][i] = 0.f;
    float m0 = -1e30f, m1 = -1e30f, l0 = 0.f, l1 = 0.f;

    for (int kt = 0; kt < nkt; kt++) {
        const int cur = kt & 1;
        if (kt + 1 < nkt) {
            const int s0n = (kt + 1) * 64;
            const int sel = cur ^ 1;
#pragma unroll
            for (int it = 0; it < 8; it++) {
                int idx = tid + it*256;
                int d = idx >> 4, c4 = (idx & 15) * 4;
                CPA16(sb + KOFF + sel*KSZ + (d*FKS + c4)*4,
                      (const void*)(kg + (long)d*T_ + s0n + c4));
            }
#pragma unroll
            for (int it = 0; it < 8; it++) {
                int idx = tid + it*256;
                int c = idx >> 5, d4 = (idx & 31) * 4;
                CPA16(sb + VOFF + sel*VSZ + (c*FVS + d4)*4,
                      (const void*)(vg + (long)(s0n + c)*(KVH_*HD_) + d4));
            }
            CP_COMMIT();
            CP_WAIT1();
        } else {
            CP_WAIT0();
        }
        __syncthreads();

        const uint32_t* Kc = (const uint32_t*)(smem + KOFF + cur*KSZ);
        const uint32_t* Vc = (const uint32_t*)(smem + VOFF + cur*VSZ);

        float sf[8][4];
#pragma unroll
        for (int nt = 0; nt < 8; nt++)
#pragma unroll
            for (int i = 0; i < 4; i++) sf[nt][i] = 0.f;

#pragma unroll
        for (int kd = 0; kd < 16; kd++) {
            uint32_t a[4];
            a[0] = Qs[(wm+g)*FQS   + kd*8 + tg];
            a[1] = Qs[(wm+g+8)*FQS + kd*8 + tg];
            a[2] = Qs[(wm+g)*FQS   + kd*8 + tg + 4];
            a[3] = Qs[(wm+g+8)*FQS + kd*8 + tg + 4];
#pragma unroll
            for (int nt = 0; nt < 8; nt++) {
                uint32_t bb[2];
                bb[0] = Kc[(kd*8+tg)*FKS   + nt*8 + g];
                bb[1] = Kc[(kd*8+tg+4)*FKS + nt*8 + g];
                mma_tf32(sf[nt], a, bb);
            }
        }

        if (kt >= nkt - 2) {
            const int s0c = kt * 64;
            const int r0 = t0 + wm + g, r1 = r0 + 8;
#pragma unroll
            for (int nt = 0; nt < 8; nt++) {
                int c0 = s0c + nt*8 + 2*tg;
                if (c0     > r0) sf[nt][0] = -1e30f;
                if (c0 + 1 > r0) sf[nt][1] = -1e30f;
                if (c0     > r1) sf[nt][2] = -1e30f;
                if (c0 + 1 > r1) sf[nt][3] = -1e30f;
            }
        }

        float mt0 = -1e30f, mt1 = -1e30f;
#pragma unroll
        for (int nt = 0; nt < 8; nt++) {
            mt0 = fmaxf(mt0, fmaxf(sf[nt][0], sf[nt][1]));
            mt1 = fmaxf(mt1, fmaxf(sf[nt][2], sf[nt][3]));
        }
        mt0 = fmaxf(mt0, __shfl_xor_sync(0xffffffffu, mt0, 1));
        mt0 = fmaxf(mt0, __shfl_xor_sync(0xffffffffu, mt0, 2));
        mt1 = fmaxf(mt1, __shfl_xor_sync(0xffffffffu, mt1, 1));
        mt1 = fmaxf(mt1, __shfl_xor_sync(0xffffffffu, mt1, 2));

        float mn0 = fmaxf(m0, mt0), mn1 = fmaxf(m1, mt1);
        float al0 = __expf(m0 - mn0), al1 = __expf(m1 - mn1);
        m0 = mn0; m1 = mn1;

        float rs0 = 0.f, rs1 = 0.f;
        uint32_t pf[8][4];
#pragma unroll
        for (int nt = 0; nt < 8; nt++) {
            float p0 = __expf(sf[nt][0] - mn0);
            float p1 = __expf(sf[nt][1] - mn0);
            float p2 = __expf(sf[nt][2] - mn1);
            float p3 = __expf(sf[nt][3] - mn1);
            rs0 += p0 + p1; rs1 += p2 + p3;
            pf[nt][0] = f2tf(p0); pf[nt][1] = f2tf(p1);
            pf[nt][2] = f2tf(p2); pf[nt][3] = f2tf(p3);
        }
        rs0 += __shfl_xor_sync(0xffffffffu, rs0, 1);
        rs0 += __shfl_xor_sync(0xffffffffu, rs0, 2);
        rs1 += __shfl_xor_sync(0xffffffffu, rs1, 1);
        rs1 += __shfl_xor_sync(0xffffffffu, rs1, 2);
        l0 = l0 * al0 + rs0;
        l1 = l1 * al1 + rs1;

#pragma unroll
        for (int nt = 0; nt < 16; nt++) {
            o[nt][0] *= al0; o[nt][1] *= al0;
            o[nt][2] *= al1; o[nt][3] *= al1;
        }

#pragma unroll
        for (int ks = 0; ks < 8; ks++) {
            const int src1 = (g << 2) | (tg >> 1);
            uint32_t u0 = __shfl_sync(0xffffffffu, pf[ks][0], src1);
            uint32_t u1 = __shfl_sync(0xffffffffu, pf[ks][1], src1);
            uint32_t u2 = __shfl_sync(0xffffffffu, pf[ks][2], src1);
            uint32_t u3 = __shfl_sync(0xffffffffu, pf[ks][3], src1);
            uint32_t w0 = __shfl_sync(0xffffffffu, pf[ks][0], src1 + 2);
            uint32_t w1 = __shfl_sync(0xffffffffu, pf[ks][1], src1 + 2);
            uint32_t w2 = __shfl_sync(0xffffffffu, pf[ks][2], src1 + 2);
            uint32_t w3 = __shfl_sync(0xffffffffu, pf[ks][3], src1 + 2);
            uint32_t a[4];
            a[0] = (tg & 1) ? u1 : u0;
            a[1] = (tg & 1) ? u3 : u2;
            a[2] = (tg & 1) ? w1 : w0;
            a[3] = (tg & 1) ? w3 : w2;
#pragma unroll
            for (int nt = 0; nt < 16; nt++) {
                uint32_t bb[2];
                bb[0] = Vc[(ks*8+tg)*FVS   + nt*8 + g];
                bb[1] = Vc[(ks*8+tg+4)*FVS + nt*8 + g];
                mma_tf32(o[nt], a, bb);
            }
        }
        __syncthreads();
    }

    const float inv0 = 1.0f / l0, inv1 = 1.0f / l1;
    float* og0 = g_O + (long)(b*T_ + t0 + wm + g) * (H_*HD_) + h*HD_;
    float* og1 = og0 + 8L * (H_*HD_);
#pragma unroll
    for (int nt = 0; nt < 16; nt++) {
        int c = nt*8 + 2*tg;
        *(float2*)(og0 + c) = make_float2(
            __uint_as_float(f2tf(o[nt][0]*inv0)),
            __uint_as_float(f2tf(o[nt][1]*inv0)));
        *(float2*)(og1 + c) = make_float2(
            __uint_as_float(f2tf(o[nt][2]*inv1)),
            __uint_as_float(f2tf(o[nt][3]*inv1)));
    }
}

// =====================================================================
// host launcher
// =====================================================================
extern "C" void kernel_launch(void* const* d_in, const int* in_sizes, int n_in,
                              void* d_out, int out_size)
{
    const float* x  = (const float*)d_in[0];
    const float* wq = (const float*)d_in[1];
    const float* bq = (const float*)d_in[2];
    const float* wk = (const float*)d_in[3];
    const float* bk = (const float*)d_in[4];
    const float* wv = (const float*)d_in[5];
    const float* bv = (const float*)d_in[6];
    const float* wo = (const float*)d_in[7];
    float* out = (float*)d_out;

    float *qp, *kp, *vp, *op;
    float *xr, *wqr, *wkr, *wvr, *wor;
    cudaGetSymbolAddress((void**)&qp, g_Q);
    cudaGetSymbolAddress((void**)&kp, g_K);
    cudaGetSymbolAddress((void**)&vp, g_V);
    cudaGetSymbolAddress((void**)&op, g_O);
    cudaGetSymbolAddress((void**)&xr,  g_Xr);
    cudaGetSymbolAddress((void**)&wqr, g_Wq);
    cudaGetSymbolAddress((void**)&wkr, g_Wk);
    cudaGetSymbolAddress((void**)&wvr, g_Wv);
    cudaGetSymbolAddress((void**)&wor, g_Wo);

    cudaFuncSetAttribute(flash_tc,
                         cudaFuncAttributeMaxDynamicSharedMemorySize, FLASH_SMEM);
    cudaFuncSetAttribute(qkv_mma,
                         cudaFuncAttributeMaxDynamicSharedMemorySize, GEMM_SMEM);
    cudaFuncSetAttribute(gemm_mma,
                         cudaFuncAttributeMaxDynamicSharedMemorySize, GEMM_SMEM);

    dim3 blk(256);

    // pre-round GEMM operands to tf32
    round_tf32_kernel<<<(MROWS*C_/4 + 255)/256,    blk>>>(x,  xr,  MROWS*C_/4);
    round_tf32_kernel<<<(C_*H_*HD_/4 + 255)/256,   blk>>>(wq, wqr, C_*H_*HD_/4);
    round_tf32_kernel<<<(C_*KVH_*HD_/4 + 255)/256, blk>>>(wk, wkr, C_*KVH_*HD_/4);
    round_tf32_kernel<<<(C_*KVH_*HD_/4 + 255)/256, blk>>>(wv, wvr, C_*KVH_*HD_/4);
    round_tf32_kernel<<<(H_*HD_*C_/4 + 255)/256,   blk>>>(wo, wor, H_*HD_*C_/4);

    // merged QKV projection (one launch, 384 CTAs)
    qkv_mma<<<dim3(24, MROWS/256), blk, GEMM_SMEM>>>(
        xr, wqr, bq, qp, wkr, bk, kp, wvr, bv, vp);

    // RoPE
    rope_q_kernel<<<(B_*T_*H_*64)/256, blk>>>();
    ropeT_k_kernel<<<dim3(T_/32, 2, B_*KVH_), blk>>>();

    // tensor-core flash attention
    flash_tc<<<dim3(T_/128, H_, B_), blk, FLASH_SMEM>>>();

    // output projection
    gemm_mma<<<dim3(C_/128, MROWS/256), blk, GEMM_SMEM>>>(op, wor, nullptr, out, C_, H_*HD_, 0);
}